// round 1
// baseline (speedup 1.0000x reference)
#include <cuda_runtime.h>
#include <math.h>

#define BATCH 4
#define DIMC 256
#define NQ 2048
#define MKV 2048
#define HEADS 8
#define DHEAD 64
#define DINNER 512

#define NEG_BIG (-3.402823466e38f)

// -------------------- scratch (device globals, no allocation) --------------------
__device__ float g_fmap_n[BATCH * DIMC * NQ];     // 8 MB
__device__ float g_ctx_n[BATCH * DIMC * MKV];     // 8 MB
__device__ float g_q[BATCH * DINNER * NQ];        // 16 MB
__device__ float g_kv[BATCH * 2 * DINNER * MKV];  // 32 MB
__device__ float g_att[BATCH * DINNER * NQ];      // 16 MB
__device__ int   g_mask_kind;                     // 0=int32, 1=uint8, 2=float32

// -------------------- mask dtype detection --------------------
// Scans first 2048 32-bit words (valid for all candidate encodings:
// u8 mask = 8192 bytes = 2048 words; i32/f32 mask >= 8192 words).
// int32 bool: every word in {0,1}. float32 bool: every word in {0, 0x3F800000}.
// uint8 random 0/1 bytes: words have high bytes set with overwhelming probability.
__global__ void detect_mask_kernel(const unsigned int* __restrict__ w) {
    __shared__ int s_i32ok, s_f32ok;
    if (threadIdx.x == 0) { s_i32ok = 1; s_f32ok = 1; }
    __syncthreads();
    int i32ok = 1, f32ok = 1;
    for (int i = threadIdx.x; i < 2048; i += 256) {
        unsigned v = w[i];
        if (v > 1u) i32ok = 0;
        if (v != 0u && v != 0x3F800000u) f32ok = 0;
    }
    if (!i32ok) atomicAnd(&s_i32ok, 0);
    if (!f32ok) atomicAnd(&s_f32ok, 0);
    __syncthreads();
    if (threadIdx.x == 0) g_mask_kind = s_i32ok ? 0 : (s_f32ok ? 2 : 1);
}

// -------------------- channel RMSNorm: F.normalize(x,dim=1)*sqrt(C)*gamma --------------------
__global__ void rmsnorm_kernel(const float* __restrict__ x, const float* __restrict__ gamma,
                               float* __restrict__ y, int C, int NN, int total) {
    int col = blockIdx.x * blockDim.x + threadIdx.x;
    if (col >= total) return;
    int b = col / NN;
    int n = col - b * NN;
    const float* xp = x + (size_t)b * C * NN + n;
    float* yp = y + (size_t)b * C * NN + n;
    float ss = 0.f;
    #pragma unroll 8
    for (int c = 0; c < C; c++) { float v = xp[(size_t)c * NN]; ss += v * v; }
    float scale = sqrtf((float)C) / fmaxf(sqrtf(ss), 1e-12f);
    #pragma unroll 8
    for (int c = 0; c < C; c++) yp[(size_t)c * NN] = xp[(size_t)c * NN] * scale * gamma[c];
}

// -------------------- batched GEMM: Y[b] = W (OxK) @ X[b] (KxNN) --------------------
// 64x64 C-tile per block, 256 threads, 4x4 microtile per thread, K-step 16.
__global__ void gemm64_kernel(const float* __restrict__ W, const float* __restrict__ X,
                              float* __restrict__ Y, int O, int K, int NN) {
    const int b = blockIdx.z;
    const float* Xb = X + (size_t)b * K * NN;
    float* Yb = Y + (size_t)b * O * NN;
    const int n0 = blockIdx.x * 64, o0 = blockIdx.y * 64;
    const int tid = threadIdx.x;
    const int tx = tid & 15, ty = tid >> 4;
    __shared__ float Ws[16 * 64];
    __shared__ float Xs[16 * 64];
    float acc[4][4] = {};
    const int o_ld = tid >> 2, kq = tid & 3;   // W-tile load mapping
    const int k_ld = tid >> 4, n4 = tid & 15;  // X-tile load mapping
    for (int k0 = 0; k0 < K; k0 += 16) {
        __syncthreads();
        float4 w4 = *(const float4*)&W[(size_t)(o0 + o_ld) * K + k0 + kq * 4];
        Ws[(kq * 4 + 0) * 64 + o_ld] = w4.x;
        Ws[(kq * 4 + 1) * 64 + o_ld] = w4.y;
        Ws[(kq * 4 + 2) * 64 + o_ld] = w4.z;
        Ws[(kq * 4 + 3) * 64 + o_ld] = w4.w;
        *(float4*)&Xs[k_ld * 64 + n4 * 4] =
            *(const float4*)&Xb[(size_t)(k0 + k_ld) * NN + n0 + n4 * 4];
        __syncthreads();
        #pragma unroll
        for (int k = 0; k < 16; k++) {
            float4 a  = *(const float4*)&Ws[k * 64 + ty * 4];
            float4 bb = *(const float4*)&Xs[k * 64 + tx * 4];
            acc[0][0] += a.x * bb.x; acc[0][1] += a.x * bb.y; acc[0][2] += a.x * bb.z; acc[0][3] += a.x * bb.w;
            acc[1][0] += a.y * bb.x; acc[1][1] += a.y * bb.y; acc[1][2] += a.y * bb.z; acc[1][3] += a.y * bb.w;
            acc[2][0] += a.z * bb.x; acc[2][1] += a.z * bb.y; acc[2][2] += a.z * bb.z; acc[2][3] += a.z * bb.w;
            acc[3][0] += a.w * bb.x; acc[3][1] += a.w * bb.y; acc[3][2] += a.w * bb.z; acc[3][3] += a.w * bb.w;
        }
    }
    #pragma unroll
    for (int i = 0; i < 4; i++) {
        float4 r = make_float4(acc[i][0], acc[i][1], acc[i][2], acc[i][3]);
        *(float4*)&Yb[(size_t)(o0 + ty * 4 + i) * NN + n0 + tx * 4] = r;
    }
}

// -------------------- fused L2-distance attention (flash-style) --------------------
// grid (NQ/64, HEADS, BATCH), 256 threads.
// smem: q_s[64][64] dd-major | k_s[64][64] dd-major | v_s[64][64] dd-major |
//       s_s[64][64] i-major  | mk_s[64]
// After the loop, q_s region is reused as o_s with stride 65 for the coalesced store.
__global__ void attn_kernel(const float* __restrict__ qb, const float* __restrict__ kvb,
                            const void* __restrict__ maskp, float* __restrict__ ob) {
    const int n0 = blockIdx.x * 64;
    const int h = blockIdx.y;
    const int b = blockIdx.z;
    extern __shared__ float sm[];
    float* q_s = sm;              // 4096
    float* k_s = sm + 4096;       // 4096
    float* v_s = sm + 8192;       // 4096
    float* s_s = sm + 12288;      // 4096
    float* mk_s = sm + 16384;     // 64
    float* o_s = sm;              // alias (stride 65, 4160 floats, fits in q_s+k_s)

    const int tid = threadIdx.x;
    const int tx = tid & 15, ty = tid >> 4;

    const float* qptr = qb + ((size_t)b * DINNER + h * DHEAD) * NQ + n0;
    const float* kptr = kvb + ((size_t)b * 2 * DINNER + h * DHEAD) * MKV;
    const float* vptr = kvb + ((size_t)b * 2 * DINNER + DINNER + h * DHEAD) * MKV;

    // load Q tile [dd][i]
    #pragma unroll
    for (int it = 0; it < 16; it++) {
        int e = it * 256 + tid;
        int dd = e >> 6, i = e & 63;
        q_s[e] = qptr[(size_t)dd * NQ + i];
    }
    __syncthreads();

    // q^2 per row (each thread for its 4 rows)
    float q2l[4] = {0.f, 0.f, 0.f, 0.f};
    #pragma unroll 8
    for (int dd = 0; dd < 64; dd++) {
        float4 qv = *(const float4*)&q_s[dd * 64 + ty * 4];
        q2l[0] += qv.x * qv.x; q2l[1] += qv.y * qv.y;
        q2l[2] += qv.z * qv.z; q2l[3] += qv.w * qv.w;
    }

    float mrow[4], lrow[4], o[4][4];
    #pragma unroll
    for (int ii = 0; ii < 4; ii++) {
        mrow[ii] = NEG_BIG; lrow[ii] = 0.f;
        #pragma unroll
        for (int dk = 0; dk < 4; dk++) o[ii][dk] = 0.f;
    }

    const int mask_kind = g_mask_kind;

    for (int m0 = 0; m0 < MKV; m0 += 64) {
        __syncthreads();  // protect k_s/v_s/s_s/mk_s from previous iteration readers
        #pragma unroll
        for (int it = 0; it < 16; it++) {
            int e = it * 256 + tid;
            int dd = e >> 6, j = e & 63;
            k_s[e] = kptr[(size_t)dd * MKV + m0 + j];
            v_s[e] = vptr[(size_t)dd * MKV + m0 + j];
        }
        if (tid < 64) {
            int j = tid;
            bool ok;
            if (mask_kind == 0)      ok = ((const int*)maskp)[(size_t)b * MKV + m0 + j] != 0;
            else if (mask_kind == 1) ok = ((const unsigned char*)maskp)[(size_t)b * MKV + m0 + j] != 0;
            else                     ok = ((const float*)maskp)[(size_t)b * MKV + m0 + j] != 0.f;
            mk_s[j] = ok ? 1.f : 0.f;
        }
        __syncthreads();

        // ---- S = -dist * scale, with k^2 folded into the dot pass ----
        float dot[4][4] = {};
        float k2l[4] = {0.f, 0.f, 0.f, 0.f};
        #pragma unroll 8
        for (int dd = 0; dd < 64; dd++) {
            float4 qv = *(const float4*)&q_s[dd * 64 + ty * 4];
            float4 kv = *(const float4*)&k_s[dd * 64 + tx * 4];
            float qa0 = qv.x, qa1 = qv.y, qa2 = qv.z, qa3 = qv.w;
            float ka0 = kv.x, ka1 = kv.y, ka2 = kv.z, ka3 = kv.w;
            k2l[0] += ka0 * ka0; k2l[1] += ka1 * ka1; k2l[2] += ka2 * ka2; k2l[3] += ka3 * ka3;
            dot[0][0] += qa0 * ka0; dot[0][1] += qa0 * ka1; dot[0][2] += qa0 * ka2; dot[0][3] += qa0 * ka3;
            dot[1][0] += qa1 * ka0; dot[1][1] += qa1 * ka1; dot[1][2] += qa1 * ka2; dot[1][3] += qa1 * ka3;
            dot[2][0] += qa2 * ka0; dot[2][1] += qa2 * ka1; dot[2][2] += qa2 * ka2; dot[2][3] += qa2 * ka3;
            dot[3][0] += qa3 * ka0; dot[3][1] += qa3 * ka1; dot[3][2] += qa3 * ka2; dot[3][3] += qa3 * ka3;
        }

        float mk0 = mk_s[tx * 4 + 0], mk1 = mk_s[tx * 4 + 1];
        float mk2 = mk_s[tx * 4 + 2], mk3 = mk_s[tx * 4 + 3];
        float mloc[4];
        #pragma unroll
        for (int ii = 0; ii < 4; ii++) {
            #pragma unroll
            for (int jj = 0; jj < 4; jj++) {
                float d2 = q2l[ii] + k2l[jj] - 2.f * dot[ii][jj];
                d2 = fmaxf(d2, 0.f);
                float s = -sqrtf(fmaxf(d2, 1e-12f)) * 0.125f;
                float mk = (jj == 0) ? mk0 : (jj == 1) ? mk1 : (jj == 2) ? mk2 : mk3;
                dot[ii][jj] = (mk != 0.f) ? s : NEG_BIG;
            }
            float mm = fmaxf(fmaxf(dot[ii][0], dot[ii][1]), fmaxf(dot[ii][2], dot[ii][3]));
            mloc[ii] = mm;
        }
        // reduce max over the 16 tx lanes (xor over tx bits, within warp)
        #pragma unroll
        for (int off = 1; off < 16; off <<= 1) {
            #pragma unroll
            for (int ii = 0; ii < 4; ii++)
                mloc[ii] = fmaxf(mloc[ii], __shfl_xor_sync(0xffffffffu, mloc[ii], off));
        }

        float corr[4], sloc[4];
        #pragma unroll
        for (int ii = 0; ii < 4; ii++) {
            float mn = fmaxf(mrow[ii], mloc[ii]);
            corr[ii] = __expf(mrow[ii] - mn);
            mrow[ii] = mn;
            sloc[ii] = 0.f;
            #pragma unroll
            for (int jj = 0; jj < 4; jj++) {
                float pv = __expf(dot[ii][jj] - mn);
                dot[ii][jj] = pv;
                sloc[ii] += pv;
            }
        }
        #pragma unroll
        for (int off = 1; off < 16; off <<= 1) {
            #pragma unroll
            for (int ii = 0; ii < 4; ii++)
                sloc[ii] += __shfl_xor_sync(0xffffffffu, sloc[ii], off);
        }
        #pragma unroll
        for (int ii = 0; ii < 4; ii++) {
            lrow[ii] = lrow[ii] * corr[ii] + sloc[ii];
            #pragma unroll
            for (int dk = 0; dk < 4; dk++) o[ii][dk] *= corr[ii];
        }

        // write P tile to smem (row-major), then PV within the same warp group
        #pragma unroll
        for (int ii = 0; ii < 4; ii++) {
            float4 pr = make_float4(dot[ii][0], dot[ii][1], dot[ii][2], dot[ii][3]);
            *(float4*)&s_s[(ty * 4 + ii) * 64 + tx * 4] = pr;
        }
        __syncwarp();

        // ---- O += P @ V^T  (v_s is [dd][j]; rotate j by tx to kill bank conflicts) ----
        #pragma unroll 4
        for (int jx = 0; jx < 64; jx++) {
            int j = (jx + tx) & 63;
            float vv0 = v_s[(tx * 4 + 0) * 64 + j];
            float vv1 = v_s[(tx * 4 + 1) * 64 + j];
            float vv2 = v_s[(tx * 4 + 2) * 64 + j];
            float vv3 = v_s[(tx * 4 + 3) * 64 + j];
            #pragma unroll
            for (int ii = 0; ii < 4; ii++) {
                float pij = s_s[(ty * 4 + ii) * 64 + j];
                o[ii][0] += pij * vv0;
                o[ii][1] += pij * vv1;
                o[ii][2] += pij * vv2;
                o[ii][3] += pij * vv3;
            }
        }
    }

    // ---- normalize and store (stage through smem for coalesced global writes) ----
    __syncthreads();
    #pragma unroll
    for (int ii = 0; ii < 4; ii++) {
        float inv = 1.0f / lrow[ii];
        #pragma unroll
        for (int dk = 0; dk < 4; dk++)
            o_s[(ty * 4 + ii) * 65 + (tx * 4 + dk)] = o[ii][dk] * inv;  // o_s[i][dd], stride 65
    }
    __syncthreads();
    #pragma unroll
    for (int it = 0; it < 16; it++) {
        int e = it * 256 + tid;
        int dd = e >> 6, i = e & 63;
        ob[((size_t)b * DINNER + h * DHEAD + dd) * NQ + n0 + i] = o_s[i * 65 + dd];
    }
}

// -------------------- launch --------------------
extern "C" void kernel_launch(void* const* d_in, const int* in_sizes, int n_in,
                              void* d_out, int out_size) {
    const float* fmap      = (const float*)d_in[0];
    const float* context   = (const float*)d_in[1];
    const void*  mask      = d_in[2];
    const float* gamma     = (const float*)d_in[3];
    const float* gamma_ctx = (const float*)d_in[4];
    const float* Wq        = (const float*)d_in[5];
    const float* Wkv       = (const float*)d_in[6];
    const float* Wout      = (const float*)d_in[7];
    float* out = (float*)d_out;

    float *p_fmap_n, *p_ctx_n, *p_q, *p_kv, *p_att;
    cudaGetSymbolAddress((void**)&p_fmap_n, g_fmap_n);
    cudaGetSymbolAddress((void**)&p_ctx_n, g_ctx_n);
    cudaGetSymbolAddress((void**)&p_q, g_q);
    cudaGetSymbolAddress((void**)&p_kv, g_kv);
    cudaGetSymbolAddress((void**)&p_att, g_att);

    cudaFuncSetAttribute(attn_kernel, cudaFuncAttributeMaxDynamicSharedMemorySize, 66048);

    // 0. mask dtype detection
    detect_mask_kernel<<<1, 256>>>((const unsigned int*)mask);

    // 1. channel RMSNorm (fmap, context)
    rmsnorm_kernel<<<(BATCH * NQ + 255) / 256, 256>>>(fmap, gamma, p_fmap_n, DIMC, NQ, BATCH * NQ);
    rmsnorm_kernel<<<(BATCH * MKV + 255) / 256, 256>>>(context, gamma_ctx, p_ctx_n, DIMC, MKV, BATCH * MKV);

    // 2. projections
    gemm64_kernel<<<dim3(NQ / 64, DINNER / 64, BATCH), 256>>>(Wq, p_fmap_n, p_q, DINNER, DIMC, NQ);
    gemm64_kernel<<<dim3(MKV / 64, 2 * DINNER / 64, BATCH), 256>>>(Wkv, p_ctx_n, p_kv, 2 * DINNER, DIMC, MKV);

    // 3. fused L2-distance attention
    attn_kernel<<<dim3(NQ / 64, HEADS, BATCH), 256, 66048>>>(p_q, p_kv, mask, p_att);

    // 4. output projection -> d_out
    gemm64_kernel<<<dim3(NQ / 64, DIMC / 64, BATCH), 256>>>(Wout, p_att, out, DIMC, DINNER, NQ);
}

// round 3
// speedup vs baseline: 1.9712x; 1.9712x over previous
#include <cuda_runtime.h>
#include <math.h>
#include <cstdint>

#define BATCH 4
#define DIMC 256
#define NQ 2048
#define MKV 2048
#define HEADS 8
#define DHEAD 64
#define DINNER 512

// ==================== scratch (device globals, no allocation) ====================
__device__ float g_fmap_n[BATCH * DIMC * NQ];     // 8 MB
__device__ float g_ctx_n[BATCH * DIMC * MKV];     // 8 MB
__device__ float g_q[BATCH * DINNER * NQ];        // 16 MB
__device__ float g_kv[BATCH * 2 * DINNER * MKV];  // 32 MB
__device__ float g_att[BATCH * DINNER * NQ];      // 16 MB
__device__ float g_qT[BATCH * DINNER * NQ];       // [b][h][n][64]
__device__ float g_kT[BATCH * DINNER * MKV];      // [b][h][m][64]
__device__ float g_vT[BATCH * DINNER * MKV];      // [b][h][m][64]
__device__ float g_q2[BATCH * HEADS * NQ];
__device__ float g_k2[BATCH * HEADS * MKV];
__device__ unsigned g_maskbits[BATCH * MKV / 32];
__device__ int   g_mask_kind;

// ==================== small helpers ====================
__device__ __forceinline__ uint32_t f2tf32(float f) {
    uint32_t r;
    asm("cvt.rna.tf32.f32 %0, %1;" : "=r"(r) : "f"(f));
    return r;
}

__device__ __forceinline__ void mma_tf32(float* d, const uint32_t* a, uint32_t b0, uint32_t b1) {
    asm volatile(
        "mma.sync.aligned.m16n8k8.row.col.f32.tf32.tf32.f32 "
        "{%0,%1,%2,%3}, {%4,%5,%6,%7}, {%8,%9}, {%0,%1,%2,%3};"
        : "+f"(d[0]), "+f"(d[1]), "+f"(d[2]), "+f"(d[3])
        : "r"(a[0]), "r"(a[1]), "r"(a[2]), "r"(a[3]), "r"(b0), "r"(b1));
}

// ==================== mask dtype detection ====================
__global__ void detect_mask_kernel(const unsigned int* __restrict__ w) {
    __shared__ int s_i32ok, s_f32ok;
    if (threadIdx.x == 0) { s_i32ok = 1; s_f32ok = 1; }
    __syncthreads();
    int i32ok = 1, f32ok = 1;
    for (int i = threadIdx.x; i < 2048; i += 256) {
        unsigned v = w[i];
        if (v > 1u) i32ok = 0;
        if (v != 0u && v != 0x3F800000u) f32ok = 0;
    }
    if (!i32ok) atomicAnd(&s_i32ok, 0);
    if (!f32ok) atomicAnd(&s_f32ok, 0);
    __syncthreads();
    if (threadIdx.x == 0) g_mask_kind = s_i32ok ? 0 : (s_f32ok ? 2 : 1);
}

__global__ void maskbits_kernel(const void* __restrict__ maskp) {
    int w = blockIdx.x * blockDim.x + threadIdx.x;
    if (w >= BATCH * MKV / 32) return;
    int kind = g_mask_kind;
    unsigned bits = 0;
    size_t base = (size_t)w * 32;
    for (int i = 0; i < 32; i++) {
        bool ok;
        if (kind == 0)      ok = ((const int*)maskp)[base + i] != 0;
        else if (kind == 1) ok = ((const unsigned char*)maskp)[base + i] != 0;
        else                ok = ((const float*)maskp)[base + i] != 0.f;
        bits |= (ok ? 1u : 0u) << i;
    }
    g_maskbits[w] = bits;
}

// ==================== channel RMSNorm ====================
__global__ void rmsnorm_kernel(const float* __restrict__ x, const float* __restrict__ gamma,
                               float* __restrict__ y, int C, int NN, int total) {
    int col = blockIdx.x * blockDim.x + threadIdx.x;
    if (col >= total) return;
    int b = col / NN;
    int n = col - b * NN;
    const float* xp = x + (size_t)b * C * NN + n;
    float* yp = y + (size_t)b * C * NN + n;
    float ss = 0.f;
    #pragma unroll 8
    for (int c = 0; c < C; c++) { float v = xp[(size_t)c * NN]; ss += v * v; }
    float scale = sqrtf((float)C) / fmaxf(sqrtf(ss), 1e-12f);
    #pragma unroll 8
    for (int c = 0; c < C; c++) yp[(size_t)c * NN] = xp[(size_t)c * NN] * scale * gamma[c];
}

// ==================== batched GEMM (fp32 CUDA-core) ====================
__global__ void gemm64_kernel(const float* __restrict__ W, const float* __restrict__ X,
                              float* __restrict__ Y, int O, int K, int NN) {
    const int b = blockIdx.z;
    const float* Xb = X + (size_t)b * K * NN;
    float* Yb = Y + (size_t)b * O * NN;
    const int n0 = blockIdx.x * 64, o0 = blockIdx.y * 64;
    const int tid = threadIdx.x;
    const int tx = tid & 15, ty = tid >> 4;
    __shared__ float Ws[16 * 64];
    __shared__ float Xs[16 * 64];
    float acc[4][4] = {};
    const int o_ld = tid >> 2, kq = tid & 3;
    const int k_ld = tid >> 4, n4 = tid & 15;
    for (int k0 = 0; k0 < K; k0 += 16) {
        __syncthreads();
        float4 w4 = *(const float4*)&W[(size_t)(o0 + o_ld) * K + k0 + kq * 4];
        Ws[(kq * 4 + 0) * 64 + o_ld] = w4.x;
        Ws[(kq * 4 + 1) * 64 + o_ld] = w4.y;
        Ws[(kq * 4 + 2) * 64 + o_ld] = w4.z;
        Ws[(kq * 4 + 3) * 64 + o_ld] = w4.w;
        *(float4*)&Xs[k_ld * 64 + n4 * 4] =
            *(const float4*)&Xb[(size_t)(k0 + k_ld) * NN + n0 + n4 * 4];
        __syncthreads();
        #pragma unroll
        for (int k = 0; k < 16; k++) {
            float4 a  = *(const float4*)&Ws[k * 64 + ty * 4];
            float4 bb = *(const float4*)&Xs[k * 64 + tx * 4];
            acc[0][0] += a.x * bb.x; acc[0][1] += a.x * bb.y; acc[0][2] += a.x * bb.z; acc[0][3] += a.x * bb.w;
            acc[1][0] += a.y * bb.x; acc[1][1] += a.y * bb.y; acc[1][2] += a.y * bb.z; acc[1][3] += a.y * bb.w;
            acc[2][0] += a.z * bb.x; acc[2][1] += a.z * bb.y; acc[2][2] += a.z * bb.z; acc[2][3] += a.z * bb.w;
            acc[3][0] += a.w * bb.x; acc[3][1] += a.w * bb.y; acc[3][2] += a.w * bb.z; acc[3][3] += a.w * bb.w;
        }
    }
    #pragma unroll
    for (int i = 0; i < 4; i++) {
        float4 r = make_float4(acc[i][0], acc[i][1], acc[i][2], acc[i][3]);
        *(float4*)&Yb[(size_t)(o0 + ty * 4 + i) * NN + n0 + tx * 4] = r;
    }
}

// ==================== transpose: [b][C][NN] -> [b][C/64][NN][64] ====================
__global__ void transpose_hd_kernel(const float* __restrict__ in, float* __restrict__ out,
                                    int C, int NN, size_t bstride) {
    __shared__ float t[32][33];
    const int b = blockIdx.z;
    const int c0 = blockIdx.y * 32;
    const int n0 = blockIdx.x * 32;
    const float* ip = in + (size_t)b * bstride;
    #pragma unroll
    for (int i = 0; i < 4; i++) {
        int c = c0 + threadIdx.y + i * 8;
        t[threadIdx.y + i * 8][threadIdx.x] = ip[(size_t)c * NN + n0 + threadIdx.x];
    }
    __syncthreads();
    int c = c0 + threadIdx.x;
    int hh = c >> 6, dd = c & 63;
    float* op = out + ((size_t)(b * (C / 64) + hh) * NN) * 64;
    #pragma unroll
    for (int i = 0; i < 4; i++) {
        int n = n0 + threadIdx.y + i * 8;
        op[(size_t)n * 64 + dd] = t[threadIdx.x][threadIdx.y + i * 8];
    }
}

// ==================== row sum of squares: x [rows][64] -> out [rows] ====================
__global__ void sumsq_kernel(const float* __restrict__ x, float* __restrict__ out, int rows) {
    int r = blockIdx.x * blockDim.x + threadIdx.x;
    if (r >= rows) return;
    const float4* p = (const float4*)(x + (size_t)r * 64);
    float s = 0.f;
    #pragma unroll
    for (int i = 0; i < 16; i++) {
        float4 v = p[i];
        s += v.x * v.x + v.y * v.y + v.z * v.z + v.w * v.w;
    }
    out[r] = s;
}

// ==================== tensor-core (mma.sync tf32) L2-distance attention ====================
// grid (NQ/64, HEADS, BATCH), 128 threads (4 warps, 16 q-rows per warp).
// smem (floats): Ks[64][76] | Vs[64][76] | Ps[64][76] (warp-private 16-row slices)
#define SMS 76
#define ATTN_SMEM_BYTES ((3 * 64 * SMS) * 4)

__global__ void __launch_bounds__(128) attn_mma_kernel(
    const float* __restrict__ qT, const float* __restrict__ kT, const float* __restrict__ vT,
    const float* __restrict__ q2g, const float* __restrict__ k2g,
    const unsigned* __restrict__ mbits, float* __restrict__ ob)
{
    extern __shared__ float sm[];
    float* Ks = sm;                       // [64][SMS], tf32 bits
    float* Vs = sm + 64 * SMS;            // [64][SMS], tf32 bits
    float* Ps = sm + 128 * SMS;           // [64][SMS], tf32 bits (P), warp slices

    const int tid = threadIdx.x;
    const int wid = tid >> 5, lane = tid & 31;
    const int gq = lane >> 2, gc = lane & 3;   // fragment row-group / col-in-group
    const int n0 = blockIdx.x * 64;
    const int h = blockIdx.y, b = blockIdx.z;
    const int bh = b * HEADS + h;
    const int qbase = n0 + wid * 16;

    // ---- Q A-fragments: converted to tf32 once, live in registers ----
    uint32_t aq[8][4];
    {
        const float* qp = qT + ((size_t)bh * NQ + qbase) * 64;
        #pragma unroll
        for (int ks = 0; ks < 8; ks++) {
            aq[ks][0] = f2tf32(qp[(size_t)gq * 64 + gc + 8 * ks]);
            aq[ks][1] = f2tf32(qp[(size_t)(gq + 8) * 64 + gc + 8 * ks]);
            aq[ks][2] = f2tf32(qp[(size_t)gq * 64 + gc + 4 + 8 * ks]);
            aq[ks][3] = f2tf32(qp[(size_t)(gq + 8) * 64 + gc + 4 + 8 * ks]);
        }
    }
    const float q2a = q2g[(size_t)bh * NQ + qbase + gq];
    const float q2b = q2g[(size_t)bh * NQ + qbase + gq + 8];
    const float* k2p = k2g + (size_t)bh * MKV;

    float oacc[8][4];
    #pragma unroll
    for (int nt = 0; nt < 8; nt++)
        #pragma unroll
        for (int i = 0; i < 4; i++) oacc[nt][i] = 0.f;
    float lA = 0.f, lB = 0.f;

    uint32_t* Pw = (uint32_t*)(Ps + wid * 16 * SMS);
    const float* kbase = kT + (size_t)bh * MKV * 64;
    const float* vbase = vT + (size_t)bh * MKV * 64;

    for (int t = 0; t < MKV / 64; t++) {
        const int m0 = t * 64;
        __syncthreads();  // prior tile's MMA reads of Ks/Vs complete
        // ---- stage K,V tiles [64 m][64 dd] -> smem (tf32 bits) ----
        #pragma unroll
        for (int it = 0; it < 8; it++) {
            int e = it * 128 + tid;
            int row = e >> 4, c4 = e & 15;
            float4 kv4 = *(const float4*)(kbase + (size_t)(m0 + row) * 64 + c4 * 4);
            uint32_t* dk = (uint32_t*)&Ks[row * SMS + c4 * 4];
            dk[0] = f2tf32(kv4.x); dk[1] = f2tf32(kv4.y); dk[2] = f2tf32(kv4.z); dk[3] = f2tf32(kv4.w);
            float4 vv4 = *(const float4*)(vbase + (size_t)(m0 + row) * 64 + c4 * 4);
            uint32_t* dv = (uint32_t*)&Vs[row * SMS + c4 * 4];
            dv[0] = f2tf32(vv4.x); dv[1] = f2tf32(vv4.y); dv[2] = f2tf32(vv4.z); dv[3] = f2tf32(vv4.w);
        }
        __syncthreads();

        // ---- S = Q @ K^T  (rows q, cols m) ----
        float sacc[8][4];
        #pragma unroll
        for (int nt = 0; nt < 8; nt++)
            #pragma unroll
            for (int i = 0; i < 4; i++) sacc[nt][i] = 0.f;
        const uint32_t* Ki = (const uint32_t*)Ks;
        #pragma unroll
        for (int ks = 0; ks < 8; ks++) {
            #pragma unroll
            for (int nt = 0; nt < 8; nt++) {
                uint32_t b0 = Ki[(gq + 8 * nt) * SMS + gc + 8 * ks];
                uint32_t b1 = Ki[(gq + 8 * nt) * SMS + gc + 4 + 8 * ks];
                mma_tf32(sacc[nt], aq[ks], b0, b1);
            }
        }

        // ---- epilogue: d2 -> -dist/8 -> exp (max statically 0, no rescale) ----
        const unsigned w0 = mbits[b * (MKV / 32) + (m0 >> 5)];
        const unsigned w1 = mbits[b * (MKV / 32) + (m0 >> 5) + 1];
        #pragma unroll
        for (int nt = 0; nt < 8; nt++) {
            const int col0 = 2 * gc + 8 * nt;
            const float k20 = k2p[m0 + col0], k21 = k2p[m0 + col0 + 1];
            const unsigned bw = (nt < 4) ? w0 : w1;
            const int sh = col0 & 31;
            const unsigned bit0 = (bw >> sh) & 1u;
            const unsigned bit1 = (bw >> (sh + 1)) & 1u;
            float d00 = fmaxf(q2a + k20 - 2.f * sacc[nt][0], 1e-12f);
            float d01 = fmaxf(q2a + k21 - 2.f * sacc[nt][1], 1e-12f);
            float d10 = fmaxf(q2b + k20 - 2.f * sacc[nt][2], 1e-12f);
            float d11 = fmaxf(q2b + k21 - 2.f * sacc[nt][3], 1e-12f);
            float s00, s01, s10, s11;
            asm("sqrt.approx.f32 %0, %1;" : "=f"(s00) : "f"(d00));
            asm("sqrt.approx.f32 %0, %1;" : "=f"(s01) : "f"(d01));
            asm("sqrt.approx.f32 %0, %1;" : "=f"(s10) : "f"(d10));
            asm("sqrt.approx.f32 %0, %1;" : "=f"(s11) : "f"(d11));
            // exp(-dist/8) = exp2(-0.18033688 * dist)
            float p00 = bit0 ? exp2f(-0.18033688011112042f * s00) : 0.f;
            float p01 = bit1 ? exp2f(-0.18033688011112042f * s01) : 0.f;
            float p10 = bit0 ? exp2f(-0.18033688011112042f * s10) : 0.f;
            float p11 = bit1 ? exp2f(-0.18033688011112042f * s11) : 0.f;
            lA += p00 + p01;
            lB += p10 + p11;
            Pw[gq * SMS + col0]           = f2tf32(p00);
            Pw[gq * SMS + col0 + 1]       = f2tf32(p01);
            Pw[(gq + 8) * SMS + col0]     = f2tf32(p10);
            Pw[(gq + 8) * SMS + col0 + 1] = f2tf32(p11);
        }
        __syncwarp();

        // ---- O += P @ V  (rows q, cols dd) ----
        const uint32_t* Vi = (const uint32_t*)Vs;
        #pragma unroll
        for (int ks = 0; ks < 8; ks++) {
            uint32_t ap[4];
            ap[0] = Pw[gq * SMS + gc + 8 * ks];
            ap[1] = Pw[(gq + 8) * SMS + gc + 8 * ks];
            ap[2] = Pw[gq * SMS + gc + 4 + 8 * ks];
            ap[3] = Pw[(gq + 8) * SMS + gc + 4 + 8 * ks];
            #pragma unroll
            for (int nt = 0; nt < 8; nt++) {
                uint32_t b0 = Vi[(gc + 8 * ks) * SMS + gq + 8 * nt];
                uint32_t b1 = Vi[(gc + 4 + 8 * ks) * SMS + gq + 8 * nt];
                mma_tf32(oacc[nt], ap, b0, b1);
            }
        }
    }

    // ---- row-sum reduce within quad, normalize, store ----
    lA += __shfl_xor_sync(0xffffffffu, lA, 1);
    lA += __shfl_xor_sync(0xffffffffu, lA, 2);
    lB += __shfl_xor_sync(0xffffffffu, lB, 1);
    lB += __shfl_xor_sync(0xffffffffu, lB, 2);
    const float iA = 1.f / lA, iB = 1.f / lB;

    float* obase = ob + ((size_t)b * DINNER + h * DHEAD) * NQ;
    const int qA = qbase + gq, qB = qA + 8;
    #pragma unroll
    for (int nt = 0; nt < 8; nt++) {
        const int dd0 = 2 * gc + 8 * nt;
        obase[(size_t)dd0 * NQ + qA]       = oacc[nt][0] * iA;
        obase[(size_t)(dd0 + 1) * NQ + qA] = oacc[nt][1] * iA;
        obase[(size_t)dd0 * NQ + qB]       = oacc[nt][2] * iB;
        obase[(size_t)(dd0 + 1) * NQ + qB] = oacc[nt][3] * iB;
    }
}

// ==================== launch ====================
extern "C" void kernel_launch(void* const* d_in, const int* in_sizes, int n_in,
                              void* d_out, int out_size) {
    const float* fmap      = (const float*)d_in[0];
    const float* context   = (const float*)d_in[1];
    const void*  mask      = d_in[2];
    const float* gamma     = (const float*)d_in[3];
    const float* gamma_ctx = (const float*)d_in[4];
    const float* Wq        = (const float*)d_in[5];
    const float* Wkv       = (const float*)d_in[6];
    const float* Wout      = (const float*)d_in[7];
    float* out = (float*)d_out;

    float *p_fmap_n, *p_ctx_n, *p_q, *p_kv, *p_att, *p_qT, *p_kT, *p_vT, *p_q2, *p_k2;
    unsigned* p_mbits;
    cudaGetSymbolAddress((void**)&p_fmap_n, g_fmap_n);
    cudaGetSymbolAddress((void**)&p_ctx_n, g_ctx_n);
    cudaGetSymbolAddress((void**)&p_q, g_q);
    cudaGetSymbolAddress((void**)&p_kv, g_kv);
    cudaGetSymbolAddress((void**)&p_att, g_att);
    cudaGetSymbolAddress((void**)&p_qT, g_qT);
    cudaGetSymbolAddress((void**)&p_kT, g_kT);
    cudaGetSymbolAddress((void**)&p_vT, g_vT);
    cudaGetSymbolAddress((void**)&p_q2, g_q2);
    cudaGetSymbolAddress((void**)&p_k2, g_k2);
    cudaGetSymbolAddress((void**)&p_mbits, g_maskbits);

    cudaFuncSetAttribute(attn_mma_kernel, cudaFuncAttributeMaxDynamicSharedMemorySize,
                         ATTN_SMEM_BYTES);

    // 0. mask dtype detection + bit packing
    detect_mask_kernel<<<1, 256>>>((const unsigned int*)mask);
    maskbits_kernel<<<1, 256>>>(mask);

    // 1. channel RMSNorm
    rmsnorm_kernel<<<(BATCH * NQ + 255) / 256, 256>>>(fmap, gamma, p_fmap_n, DIMC, NQ, BATCH * NQ);
    rmsnorm_kernel<<<(BATCH * MKV + 255) / 256, 256>>>(context, gamma_ctx, p_ctx_n, DIMC, MKV, BATCH * MKV);

    // 2. projections (fp32)
    gemm64_kernel<<<dim3(NQ / 64, DINNER / 64, BATCH), 256>>>(Wq, p_fmap_n, p_q, DINNER, DIMC, NQ);
    gemm64_kernel<<<dim3(MKV / 64, 2 * DINNER / 64, BATCH), 256>>>(Wkv, p_ctx_n, p_kv, 2 * DINNER, DIMC, MKV);

    // 3. transpose Q, K, V to [b][h][n|m][64]
    transpose_hd_kernel<<<dim3(NQ / 32, DINNER / 32, BATCH), dim3(32, 8)>>>(
        p_q, p_qT, DINNER, NQ, (size_t)DINNER * NQ);
    transpose_hd_kernel<<<dim3(MKV / 32, DINNER / 32, BATCH), dim3(32, 8)>>>(
        p_kv, p_kT, DINNER, MKV, (size_t)2 * DINNER * MKV);
    transpose_hd_kernel<<<dim3(MKV / 32, DINNER / 32, BATCH), dim3(32, 8)>>>(
        p_kv + (size_t)DINNER * MKV, p_vT, DINNER, MKV, (size_t)2 * DINNER * MKV);

    // 4. q^2 / k^2 row sums
    sumsq_kernel<<<(BATCH * HEADS * NQ + 255) / 256, 256>>>(p_qT, p_q2, BATCH * HEADS * NQ);
    sumsq_kernel<<<(BATCH * HEADS * MKV + 255) / 256, 256>>>(p_kT, p_k2, BATCH * HEADS * MKV);

    // 5. fused tensor-core attention (mma.sync tf32)
    attn_mma_kernel<<<dim3(NQ / 64, HEADS, BATCH), 128, ATTN_SMEM_BYTES>>>(
        p_qT, p_kT, p_vT, p_q2, p_k2, p_mbits, p_att);

    // 6. output projection -> d_out
    gemm64_kernel<<<dim3(NQ / 64, DIMC / 64, BATCH), 256>>>(Wout, p_att, out, DIMC, DINNER, NQ);
}

// round 4
// speedup vs baseline: 2.0352x; 1.0325x over previous
#include <cuda_runtime.h>
#include <math.h>
#include <cstdint>

#define BATCH 4
#define DIMC 256
#define NQ 2048
#define MKV 2048
#define HEADS 8
#define DHEAD 64
#define DINNER 512

// ==================== scratch (device globals, no allocation) ====================
__device__ float g_att[BATCH * DINNER * NQ];      // attention output [b][o][n]
__device__ float g_qT[BATCH * DINNER * NQ];       // [b][h][n][64]
__device__ float g_kT[BATCH * DINNER * MKV];      // [b][h][m][64]
__device__ float g_vT[BATCH * DINNER * MKV];      // [b][h][m][64]
__device__ float g_q2[BATCH * HEADS * NQ];
__device__ float g_k2[BATCH * HEADS * MKV];
__device__ float g_sn_f[BATCH * NQ];              // per-column scale for fmap
__device__ float g_sn_c[BATCH * MKV];             // per-column scale for context
__device__ float g_Wq_g[DINNER * DIMC];           // Wq * gamma
__device__ float g_Wkv_g[2 * DINNER * DIMC];      // Wkv * gamma_ctx
__device__ unsigned g_maskbits[BATCH * MKV / 32];
__device__ int   g_mask_kind;

// ==================== small helpers ====================
__device__ __forceinline__ uint32_t f2tf32(float f) {
    uint32_t r;
    asm("cvt.rna.tf32.f32 %0, %1;" : "=r"(r) : "f"(f));
    return r;
}

__device__ __forceinline__ void mma_tf32(float* d, const uint32_t* a, uint32_t b0, uint32_t b1) {
    asm volatile(
        "mma.sync.aligned.m16n8k8.row.col.f32.tf32.tf32.f32 "
        "{%0,%1,%2,%3}, {%4,%5,%6,%7}, {%8,%9}, {%0,%1,%2,%3};"
        : "+f"(d[0]), "+f"(d[1]), "+f"(d[2]), "+f"(d[3])
        : "r"(a[0]), "r"(a[1]), "r"(a[2]), "r"(a[3]), "r"(b0), "r"(b1));
}

// ==================== mask dtype detection + packing ====================
__global__ void detect_mask_kernel(const unsigned int* __restrict__ w) {
    __shared__ int s_i32ok, s_f32ok;
    if (threadIdx.x == 0) { s_i32ok = 1; s_f32ok = 1; }
    __syncthreads();
    int i32ok = 1, f32ok = 1;
    for (int i = threadIdx.x; i < 2048; i += 256) {
        unsigned v = w[i];
        if (v > 1u) i32ok = 0;
        if (v != 0u && v != 0x3F800000u) f32ok = 0;
    }
    if (!i32ok) atomicAnd(&s_i32ok, 0);
    if (!f32ok) atomicAnd(&s_f32ok, 0);
    __syncthreads();
    if (threadIdx.x == 0) g_mask_kind = s_i32ok ? 0 : (s_f32ok ? 2 : 1);
}

__global__ void maskbits_kernel(const void* __restrict__ maskp) {
    int w = blockIdx.x * blockDim.x + threadIdx.x;
    if (w >= BATCH * MKV / 32) return;
    int kind = g_mask_kind;
    unsigned bits = 0;
    size_t base = (size_t)w * 32;
    for (int i = 0; i < 32; i++) {
        bool ok;
        if (kind == 0)      ok = ((const int*)maskp)[base + i] != 0;
        else if (kind == 1) ok = ((const unsigned char*)maskp)[base + i] != 0;
        else                ok = ((const float*)maskp)[base + i] != 0.f;
        bits |= (ok ? 1u : 0u) << i;
    }
    g_maskbits[w] = bits;
}

// ==================== per-column norm scale: s[n]=sqrt(C)/max(||x[:,n]||,eps) ====================
__global__ void colscale_kernel(const float* __restrict__ x, float* __restrict__ s, int NN) {
    __shared__ float red[4][64];
    const int b = blockIdx.y;
    const int n0 = blockIdx.x * 64;
    const int tx = threadIdx.x & 63, ty = threadIdx.x >> 6;
    const float* xp = x + (size_t)b * DIMC * NN + n0 + tx;
    float acc = 0.f;
    for (int c = ty; c < DIMC; c += 4) { float v = xp[(size_t)c * NN]; acc += v * v; }
    red[ty][tx] = acc;
    __syncthreads();
    if (ty == 0) {
        float t = red[0][tx] + red[1][tx] + red[2][tx] + red[3][tx];
        s[(size_t)b * NN + n0 + tx] = 16.0f / fmaxf(sqrtf(t), 1e-12f);
    }
}

// ==================== weight * gamma (fold channel gamma into projection) ====================
__global__ void wgamma_kernel(const float* __restrict__ W, const float* __restrict__ g,
                              float* __restrict__ Wg, int total) {
    int i = blockIdx.x * blockDim.x + threadIdx.x;
    if (i < total) Wg[i] = W[i] * g[i & (DIMC - 1)];
}

// ==================== projection GEMM + transpose + sumsq epilogue ====================
// Y tile [64 o][64 n] = Wg @ X, scaled by s[n]; stored transposed [bh][n][64];
// per-n sum of squares written when writeSq.
__global__ void gemmT_kernel(const float* __restrict__ W, const float* __restrict__ X,
                             const float* __restrict__ sn, float* __restrict__ outK,
                             float* __restrict__ outV, float* __restrict__ sq,
                             int K, int NN) {
    const int b = blockIdx.z;
    const float* Xb = X + (size_t)b * K * NN;
    const int n0 = blockIdx.x * 64, o0 = blockIdx.y * 64;
    const int tid = threadIdx.x;
    const int tx = tid & 15, ty = tid >> 4;
    __shared__ float Ws[16 * 64];
    __shared__ float Xs[16 * 64];
    __shared__ float Ts[64 * 68];
    float acc[4][4] = {};
    const int o_ld = tid >> 2, kq = tid & 3;
    const int k_ld = tid >> 4, n4 = tid & 15;
    for (int k0 = 0; k0 < K; k0 += 16) {
        __syncthreads();
        float4 w4 = *(const float4*)&W[(size_t)(o0 + o_ld) * K + k0 + kq * 4];
        Ws[(kq * 4 + 0) * 64 + o_ld] = w4.x;
        Ws[(kq * 4 + 1) * 64 + o_ld] = w4.y;
        Ws[(kq * 4 + 2) * 64 + o_ld] = w4.z;
        Ws[(kq * 4 + 3) * 64 + o_ld] = w4.w;
        *(float4*)&Xs[k_ld * 64 + n4 * 4] =
            *(const float4*)&Xb[(size_t)(k0 + k_ld) * NN + n0 + n4 * 4];
        __syncthreads();
        #pragma unroll
        for (int k = 0; k < 16; k++) {
            float4 a  = *(const float4*)&Ws[k * 64 + ty * 4];
            float4 bb = *(const float4*)&Xs[k * 64 + tx * 4];
            acc[0][0] += a.x * bb.x; acc[0][1] += a.x * bb.y; acc[0][2] += a.x * bb.z; acc[0][3] += a.x * bb.w;
            acc[1][0] += a.y * bb.x; acc[1][1] += a.y * bb.y; acc[1][2] += a.y * bb.z; acc[1][3] += a.y * bb.w;
            acc[2][0] += a.z * bb.x; acc[2][1] += a.z * bb.y; acc[2][2] += a.z * bb.z; acc[2][3] += a.z * bb.w;
            acc[3][0] += a.w * bb.x; acc[3][1] += a.w * bb.y; acc[3][2] += a.w * bb.z; acc[3][3] += a.w * bb.w;
        }
    }
    // scale by per-column norm factor, stage transposed [n][o]
    const float* sb = sn + (size_t)b * NN + n0 + tx * 4;
    float s0 = sb[0], s1 = sb[1], s2 = sb[2], s3 = sb[3];
    __syncthreads();
    #pragma unroll
    for (int i = 0; i < 4; i++) {
        Ts[(tx * 4 + 0) * 68 + ty * 4 + i] = acc[i][0] * s0;
        Ts[(tx * 4 + 1) * 68 + ty * 4 + i] = acc[i][1] * s1;
        Ts[(tx * 4 + 2) * 68 + ty * 4 + i] = acc[i][2] * s2;
        Ts[(tx * 4 + 3) * 68 + ty * 4 + i] = acc[i][3] * s3;
    }
    __syncthreads();
    const int head = blockIdx.y & 7;
    float* dst = (blockIdx.y < 8) ? outK : outV;
    float* op = dst + (((size_t)(b * HEADS + head) * NN) + n0) * 64;
    #pragma unroll
    for (int it = 0; it < 4; it++) {
        int e = it * 256 + tid;
        int row = e >> 4, c4 = e & 15;
        *(float4*)&op[(size_t)row * 64 + c4 * 4] = *(const float4*)&Ts[row * 68 + c4 * 4];
    }
    if (blockIdx.y < 8 && sq != nullptr && tid < 64) {
        float ssum = 0.f;
        #pragma unroll
        for (int i = 0; i < 16; i++) {
            float4 v = *(const float4*)&Ts[tid * 68 + i * 4];
            ssum += v.x * v.x + v.y * v.y + v.z * v.z + v.w * v.w;
        }
        sq[(size_t)(b * HEADS + head) * NN + n0 + tid] = ssum;
    }
}

// ==================== plain batched GEMM (output projection) ====================
__global__ void gemm64_kernel(const float* __restrict__ W, const float* __restrict__ X,
                              float* __restrict__ Y, int O, int K, int NN) {
    const int b = blockIdx.z;
    const float* Xb = X + (size_t)b * K * NN;
    float* Yb = Y + (size_t)b * O * NN;
    const int n0 = blockIdx.x * 64, o0 = blockIdx.y * 64;
    const int tid = threadIdx.x;
    const int tx = tid & 15, ty = tid >> 4;
    __shared__ float Ws[16 * 64];
    __shared__ float Xs[16 * 64];
    float acc[4][4] = {};
    const int o_ld = tid >> 2, kq = tid & 3;
    const int k_ld = tid >> 4, n4 = tid & 15;
    for (int k0 = 0; k0 < K; k0 += 16) {
        __syncthreads();
        float4 w4 = *(const float4*)&W[(size_t)(o0 + o_ld) * K + k0 + kq * 4];
        Ws[(kq * 4 + 0) * 64 + o_ld] = w4.x;
        Ws[(kq * 4 + 1) * 64 + o_ld] = w4.y;
        Ws[(kq * 4 + 2) * 64 + o_ld] = w4.z;
        Ws[(kq * 4 + 3) * 64 + o_ld] = w4.w;
        *(float4*)&Xs[k_ld * 64 + n4 * 4] =
            *(const float4*)&Xb[(size_t)(k0 + k_ld) * NN + n0 + n4 * 4];
        __syncthreads();
        #pragma unroll
        for (int k = 0; k < 16; k++) {
            float4 a  = *(const float4*)&Ws[k * 64 + ty * 4];
            float4 bb = *(const float4*)&Xs[k * 64 + tx * 4];
            acc[0][0] += a.x * bb.x; acc[0][1] += a.x * bb.y; acc[0][2] += a.x * bb.z; acc[0][3] += a.x * bb.w;
            acc[1][0] += a.y * bb.x; acc[1][1] += a.y * bb.y; acc[1][2] += a.y * bb.z; acc[1][3] += a.y * bb.w;
            acc[2][0] += a.z * bb.x; acc[2][1] += a.z * bb.y; acc[2][2] += a.z * bb.z; acc[2][3] += a.z * bb.w;
            acc[3][0] += a.w * bb.x; acc[3][1] += a.w * bb.y; acc[3][2] += a.w * bb.z; acc[3][3] += a.w * bb.w;
        }
    }
    #pragma unroll
    for (int i = 0; i < 4; i++) {
        float4 r = make_float4(acc[i][0], acc[i][1], acc[i][2], acc[i][3]);
        *(float4*)&Yb[(size_t)(o0 + ty * 4 + i) * NN + n0 + tx * 4] = r;
    }
}

// ==================== tensor-core (mma.sync tf32) L2-distance attention ====================
// grid (NQ/128, HEADS, BATCH), 256 threads (8 warps, 16 q-rows per warp).
// smem (floats): Ks[64][76] | Vs[64][76] | Ps[8 warps][16][76]
#define SMS 76
#define ATTN_SMEM_BYTES (256 * SMS * 4)

__global__ void __launch_bounds__(256) attn_mma_kernel(
    const float* __restrict__ qT, const float* __restrict__ kT, const float* __restrict__ vT,
    const float* __restrict__ q2g, const float* __restrict__ k2g,
    const unsigned* __restrict__ mbits, float* __restrict__ ob)
{
    extern __shared__ float sm[];
    float* Ks = sm;                       // [64][SMS]
    float* Vs = sm + 64 * SMS;            // [64][SMS]
    float* Ps = sm + 128 * SMS;           // [8][16][SMS]

    const int tid = threadIdx.x;
    const int wid = tid >> 5, lane = tid & 31;
    const int gq = lane >> 2, gc = lane & 3;
    const int n0 = blockIdx.x * 128;
    const int h = blockIdx.y, b = blockIdx.z;
    const int bh = b * HEADS + h;
    const int qbase = n0 + wid * 16;

    // ---- Q A-fragments: tf32, register-resident for all KV tiles ----
    uint32_t aq[8][4];
    {
        const float* qp = qT + ((size_t)bh * NQ + qbase) * 64;
        #pragma unroll
        for (int ks = 0; ks < 8; ks++) {
            aq[ks][0] = f2tf32(qp[(size_t)gq * 64 + gc + 8 * ks]);
            aq[ks][1] = f2tf32(qp[(size_t)(gq + 8) * 64 + gc + 8 * ks]);
            aq[ks][2] = f2tf32(qp[(size_t)gq * 64 + gc + 4 + 8 * ks]);
            aq[ks][3] = f2tf32(qp[(size_t)(gq + 8) * 64 + gc + 4 + 8 * ks]);
        }
    }
    const float q2a = q2g[(size_t)bh * NQ + qbase + gq];
    const float q2b = q2g[(size_t)bh * NQ + qbase + gq + 8];
    const float* k2p = k2g + (size_t)bh * MKV;

    float oacc[8][4];
    #pragma unroll
    for (int nt = 0; nt < 8; nt++)
        #pragma unroll
        for (int i = 0; i < 4; i++) oacc[nt][i] = 0.f;
    float lA = 0.f, lB = 0.f;

    uint32_t* Pw = (uint32_t*)(Ps + wid * 16 * SMS);
    const float* kbase = kT + (size_t)bh * MKV * 64;
    const float* vbase = vT + (size_t)bh * MKV * 64;

    for (int t = 0; t < MKV / 64; t++) {
        const int m0 = t * 64;
        __syncthreads();
        // ---- stage K,V tiles [64 m][64 dd] -> smem (tf32 bits) ----
        #pragma unroll
        for (int it = 0; it < 4; it++) {
            int e = it * 256 + tid;
            int row = e >> 4, c4 = e & 15;
            float4 kv4 = *(const float4*)(kbase + (size_t)(m0 + row) * 64 + c4 * 4);
            uint32_t* dk = (uint32_t*)&Ks[row * SMS + c4 * 4];
            dk[0] = f2tf32(kv4.x); dk[1] = f2tf32(kv4.y); dk[2] = f2tf32(kv4.z); dk[3] = f2tf32(kv4.w);
            float4 vv4 = *(const float4*)(vbase + (size_t)(m0 + row) * 64 + c4 * 4);
            uint32_t* dv = (uint32_t*)&Vs[row * SMS + c4 * 4];
            dv[0] = f2tf32(vv4.x); dv[1] = f2tf32(vv4.y); dv[2] = f2tf32(vv4.z); dv[3] = f2tf32(vv4.w);
        }
        __syncthreads();

        // ---- S = Q @ K^T ----
        float sacc[8][4];
        #pragma unroll
        for (int nt = 0; nt < 8; nt++)
            #pragma unroll
            for (int i = 0; i < 4; i++) sacc[nt][i] = 0.f;
        const uint32_t* Ki = (const uint32_t*)Ks;
        #pragma unroll
        for (int ks = 0; ks < 8; ks++) {
            #pragma unroll
            for (int nt = 0; nt < 8; nt++) {
                uint32_t b0 = Ki[(gq + 8 * nt) * SMS + gc + 8 * ks];
                uint32_t b1 = Ki[(gq + 8 * nt) * SMS + gc + 4 + 8 * ks];
                mma_tf32(sacc[nt], aq[ks], b0, b1);
            }
        }

        // ---- epilogue: d2 -> -dist/8 -> exp (sim <= 0 always, so no online max) ----
        const unsigned w0 = mbits[b * (MKV / 32) + (m0 >> 5)];
        const unsigned w1 = mbits[b * (MKV / 32) + (m0 >> 5) + 1];
        #pragma unroll
        for (int nt = 0; nt < 8; nt++) {
            const int col0 = 2 * gc + 8 * nt;
            const float k20 = k2p[m0 + col0], k21 = k2p[m0 + col0 + 1];
            const unsigned bw = (nt < 4) ? w0 : w1;
            const int sh = col0 & 31;
            const unsigned bit0 = (bw >> sh) & 1u;
            const unsigned bit1 = (bw >> (sh + 1)) & 1u;
            float d00 = fmaxf(q2a + k20 - 2.f * sacc[nt][0], 1e-12f);
            float d01 = fmaxf(q2a + k21 - 2.f * sacc[nt][1], 1e-12f);
            float d10 = fmaxf(q2b + k20 - 2.f * sacc[nt][2], 1e-12f);
            float d11 = fmaxf(q2b + k21 - 2.f * sacc[nt][3], 1e-12f);
            float s00, s01, s10, s11;
            asm("sqrt.approx.f32 %0, %1;" : "=f"(s00) : "f"(d00));
            asm("sqrt.approx.f32 %0, %1;" : "=f"(s01) : "f"(d01));
            asm("sqrt.approx.f32 %0, %1;" : "=f"(s10) : "f"(d10));
            asm("sqrt.approx.f32 %0, %1;" : "=f"(s11) : "f"(d11));
            float p00 = bit0 ? exp2f(-0.18033688011112042f * s00) : 0.f;
            float p01 = bit1 ? exp2f(-0.18033688011112042f * s01) : 0.f;
            float p10 = bit0 ? exp2f(-0.18033688011112042f * s10) : 0.f;
            float p11 = bit1 ? exp2f(-0.18033688011112042f * s11) : 0.f;
            lA += p00 + p01;
            lB += p10 + p11;
            Pw[gq * SMS + col0]           = f2tf32(p00);
            Pw[gq * SMS + col0 + 1]       = f2tf32(p01);
            Pw[(gq + 8) * SMS + col0]     = f2tf32(p10);
            Pw[(gq + 8) * SMS + col0 + 1] = f2tf32(p11);
        }
        __syncwarp();

        // ---- O += P @ V ----
        const uint32_t* Vi = (const uint32_t*)Vs;
        #pragma unroll
        for (int ks = 0; ks < 8; ks++) {
            uint32_t ap[4];
            ap[0] = Pw[gq * SMS + gc + 8 * ks];
            ap[1] = Pw[(gq + 8) * SMS + gc + 8 * ks];
            ap[2] = Pw[gq * SMS + gc + 4 + 8 * ks];
            ap[3] = Pw[(gq + 8) * SMS + gc + 4 + 8 * ks];
            #pragma unroll
            for (int nt = 0; nt < 8; nt++) {
                uint32_t b0 = Vi[(gc + 8 * ks) * SMS + gq + 8 * nt];
                uint32_t b1 = Vi[(gc + 4 + 8 * ks) * SMS + gq + 8 * nt];
                mma_tf32(oacc[nt], ap, b0, b1);
            }
        }
    }

    // ---- row-sum reduce within quad, normalize, store ----
    lA += __shfl_xor_sync(0xffffffffu, lA, 1);
    lA += __shfl_xor_sync(0xffffffffu, lA, 2);
    lB += __shfl_xor_sync(0xffffffffu, lB, 1);
    lB += __shfl_xor_sync(0xffffffffu, lB, 2);
    const float iA = 1.f / lA, iB = 1.f / lB;

    float* obase = ob + ((size_t)b * DINNER + h * DHEAD) * NQ;
    const int qA = qbase + gq, qB = qA + 8;
    #pragma unroll
    for (int nt = 0; nt < 8; nt++) {
        const int dd0 = 2 * gc + 8 * nt;
        obase[(size_t)dd0 * NQ + qA]       = oacc[nt][0] * iA;
        obase[(size_t)(dd0 + 1) * NQ + qA] = oacc[nt][1] * iA;
        obase[(size_t)dd0 * NQ + qB]       = oacc[nt][2] * iB;
        obase[(size_t)(dd0 + 1) * NQ + qB] = oacc[nt][3] * iB;
    }
}

// ==================== launch ====================
extern "C" void kernel_launch(void* const* d_in, const int* in_sizes, int n_in,
                              void* d_out, int out_size) {
    const float* fmap      = (const float*)d_in[0];
    const float* context   = (const float*)d_in[1];
    const void*  mask      = d_in[2];
    const float* gamma     = (const float*)d_in[3];
    const float* gamma_ctx = (const float*)d_in[4];
    const float* Wq        = (const float*)d_in[5];
    const float* Wkv       = (const float*)d_in[6];
    const float* Wout      = (const float*)d_in[7];
    float* out = (float*)d_out;

    float *p_att, *p_qT, *p_kT, *p_vT, *p_q2, *p_k2, *p_snf, *p_snc, *p_Wqg, *p_Wkvg;
    unsigned* p_mbits;
    cudaGetSymbolAddress((void**)&p_att, g_att);
    cudaGetSymbolAddress((void**)&p_qT, g_qT);
    cudaGetSymbolAddress((void**)&p_kT, g_kT);
    cudaGetSymbolAddress((void**)&p_vT, g_vT);
    cudaGetSymbolAddress((void**)&p_q2, g_q2);
    cudaGetSymbolAddress((void**)&p_k2, g_k2);
    cudaGetSymbolAddress((void**)&p_snf, g_sn_f);
    cudaGetSymbolAddress((void**)&p_snc, g_sn_c);
    cudaGetSymbolAddress((void**)&p_Wqg, g_Wq_g);
    cudaGetSymbolAddress((void**)&p_Wkvg, g_Wkv_g);
    cudaGetSymbolAddress((void**)&p_mbits, g_maskbits);

    cudaFuncSetAttribute(attn_mma_kernel, cudaFuncAttributeMaxDynamicSharedMemorySize,
                         ATTN_SMEM_BYTES);

    // 0. mask dtype detection + bit packing
    detect_mask_kernel<<<1, 256>>>((const unsigned int*)mask);
    maskbits_kernel<<<1, 256>>>(mask);

    // 1. per-column norm scales + gamma-folded weights
    colscale_kernel<<<dim3(NQ / 64, BATCH), 256>>>(fmap, p_snf, NQ);
    colscale_kernel<<<dim3(MKV / 64, BATCH), 256>>>(context, p_snc, MKV);
    wgamma_kernel<<<(DINNER * DIMC + 255) / 256, 256>>>(Wq, gamma, p_Wqg, DINNER * DIMC);
    wgamma_kernel<<<(2 * DINNER * DIMC + 255) / 256, 256>>>(Wkv, gamma_ctx, p_Wkvg, 2 * DINNER * DIMC);

    // 2. fused projection + scale + transpose + sumsq
    gemmT_kernel<<<dim3(NQ / 64, HEADS, BATCH), 256>>>(
        p_Wqg, fmap, p_snf, p_qT, p_qT, p_q2, DIMC, NQ);
    gemmT_kernel<<<dim3(MKV / 64, 2 * HEADS, BATCH), 256>>>(
        p_Wkvg, context, p_snc, p_kT, p_vT, p_k2, DIMC, MKV);

    // 3. fused tensor-core attention (mma.sync tf32), 128 q-rows per block
    attn_mma_kernel<<<dim3(NQ / 128, HEADS, BATCH), 256, ATTN_SMEM_BYTES>>>(
        p_qT, p_kT, p_vT, p_q2, p_k2, p_mbits, p_att);

    // 4. output projection -> d_out
    gemm64_kernel<<<dim3(NQ / 64, DIMC / 64, BATCH), 256>>>(Wout, p_att, out, DIMC, DINNER, NQ);
}

// round 5
// speedup vs baseline: 2.1648x; 1.0637x over previous
#include <cuda_runtime.h>
#include <math.h>
#include <cstdint>

#define BATCH 4
#define DIMC 256
#define NQ 2048
#define MKV 2048
#define HEADS 8
#define DHEAD 64
#define DINNER 512

// ==================== scratch (device globals, no allocation) ====================
__device__ float g_att[BATCH * DINNER * NQ];      // attention output [b][o][n]
__device__ float g_qT[BATCH * DINNER * NQ];       // [b][h][n][64]
__device__ float g_kT[BATCH * DINNER * MKV];      // [b][h][m][64]
__device__ float g_vT[BATCH * DINNER * MKV];      // [b][h][m][64]
__device__ float g_q2[BATCH * HEADS * NQ];
__device__ float g_k2[BATCH * HEADS * MKV];
__device__ float g_sn_f[BATCH * NQ];              // per-column scale for fmap
__device__ float g_sn_c[BATCH * MKV];             // per-column scale for context
__device__ float g_Wq_g[DINNER * DIMC];           // Wq * gamma
__device__ float g_Wkv_g[2 * DINNER * DIMC];      // Wkv * gamma_ctx
__device__ unsigned g_maskbits[BATCH * MKV / 32];
__device__ int   g_mask_kind;

// ==================== small helpers ====================
__device__ __forceinline__ uint32_t f2tf32(float f) {
    uint32_t r;
    asm("cvt.rna.tf32.f32 %0, %1;" : "=r"(r) : "f"(f));
    return r;
}

__device__ __forceinline__ void mma_tf32(float* d, const uint32_t* a, uint32_t b0, uint32_t b1) {
    asm volatile(
        "mma.sync.aligned.m16n8k8.row.col.f32.tf32.tf32.f32 "
        "{%0,%1,%2,%3}, {%4,%5,%6,%7}, {%8,%9}, {%0,%1,%2,%3};"
        : "+f"(d[0]), "+f"(d[1]), "+f"(d[2]), "+f"(d[3])
        : "r"(a[0]), "r"(a[1]), "r"(a[2]), "r"(a[3]), "r"(b0), "r"(b1));
}

// ==================== mask dtype detection + packing ====================
__global__ void detect_mask_kernel(const unsigned int* __restrict__ w) {
    __shared__ int s_i32ok, s_f32ok;
    if (threadIdx.x == 0) { s_i32ok = 1; s_f32ok = 1; }
    __syncthreads();
    int i32ok = 1, f32ok = 1;
    for (int i = threadIdx.x; i < 2048; i += 256) {
        unsigned v = w[i];
        if (v > 1u) i32ok = 0;
        if (v != 0u && v != 0x3F800000u) f32ok = 0;
    }
    if (!i32ok) atomicAnd(&s_i32ok, 0);
    if (!f32ok) atomicAnd(&s_f32ok, 0);
    __syncthreads();
    if (threadIdx.x == 0) g_mask_kind = s_i32ok ? 0 : (s_f32ok ? 2 : 1);
}

__global__ void maskbits_kernel(const void* __restrict__ maskp) {
    int w = blockIdx.x * blockDim.x + threadIdx.x;
    if (w >= BATCH * MKV / 32) return;
    int kind = g_mask_kind;
    unsigned bits = 0;
    size_t base = (size_t)w * 32;
    for (int i = 0; i < 32; i++) {
        bool ok;
        if (kind == 0)      ok = ((const int*)maskp)[base + i] != 0;
        else if (kind == 1) ok = ((const unsigned char*)maskp)[base + i] != 0;
        else                ok = ((const float*)maskp)[base + i] != 0.f;
        bits |= (ok ? 1u : 0u) << i;
    }
    g_maskbits[w] = bits;
}

// ==================== per-column norm scale: s[n]=sqrt(C)/max(||x[:,n]||,eps) ====================
__global__ void colscale_kernel(const float* __restrict__ x, float* __restrict__ s, int NN) {
    __shared__ float red[16][17];
    const int b = blockIdx.y;
    const int n0 = blockIdx.x * 16;
    const int tx = threadIdx.x & 15, ty = threadIdx.x >> 4;
    const float* xp = x + (size_t)b * DIMC * NN + n0 + tx;
    float acc = 0.f;
    #pragma unroll
    for (int c = ty; c < DIMC; c += 16) { float v = xp[(size_t)c * NN]; acc += v * v; }
    red[ty][tx] = acc;
    __syncthreads();
    if (ty == 0) {
        float t = 0.f;
        #pragma unroll
        for (int i = 0; i < 16; i++) t += red[i][tx];
        s[(size_t)b * NN + n0 + tx] = 16.0f / fmaxf(sqrtf(t), 1e-12f);
    }
}

// ==================== weight * gamma (fold channel gamma into projection) ====================
__global__ void wgamma_kernel(const float* __restrict__ W, const float* __restrict__ g,
                              float* __restrict__ Wg, int total) {
    int i = blockIdx.x * blockDim.x + threadIdx.x;
    if (i < total) Wg[i] = W[i] * g[i & (DIMC - 1)];
}

// ==================== tf32 mma projection GEMM + scale + transpose + sumsq ====================
// Block: 256 thr (8 warps = 4 o-quarters x 2 n-halves). Tile: 64 o (one head) x 128 n.
// C[o][n] = sum_k W[o0+o][k] * X[k][n0+n], scaled by sn[n], stored transposed [bh][n][64].
#define PSM 33
#define PROJ_SMEM (128 * 68 * 4)   // Ts overlay is the max user

__global__ void __launch_bounds__(256) projtc_kernel(
    const float* __restrict__ W, const float* __restrict__ X,
    const float* __restrict__ sn, float* __restrict__ outA, float* __restrict__ outB,
    float* __restrict__ sq, int NN)
{
    extern __shared__ float ps[];
    float* Ws = ps;                 // [64][33]
    float* Xs = ps + 64 * PSM;      // [128][33] (transposed X)
    float* Ts = ps;                 // [128][68] overlay (after MMA loop)

    const int tid = threadIdx.x;
    const int wid = tid >> 5, lane = tid & 31;
    const int gq = lane >> 2, gc = lane & 3;
    const int ow = wid & 3, nw = wid >> 2;
    const int n0 = blockIdx.x * 128;
    const int ob = blockIdx.y;
    const int o0 = ob * 64;
    const int b = blockIdx.z;
    const float* Xb = X + (size_t)b * DIMC * NN;

    float cacc[8][4];
    #pragma unroll
    for (int nt = 0; nt < 8; nt++)
        #pragma unroll
        for (int i = 0; i < 4; i++) cacc[nt][i] = 0.f;

    for (int k0 = 0; k0 < DIMC; k0 += 32) {
        __syncthreads();
        // Ws: 64 rows x 32 k (row-major, coalesced along k)
        #pragma unroll
        for (int it = 0; it < 8; it++) {
            int e = it * 256 + tid;
            int r = e >> 5, c = e & 31;
            Ws[r * PSM + c] = __uint_as_float(f2tf32(W[(size_t)(o0 + r) * DIMC + k0 + c]));
        }
        // Xs transposed: load X[k][n] coalesced, store [n][k]
        #pragma unroll
        for (int it = 0; it < 16; it++) {
            int e = it * 256 + tid;
            int kk = e >> 7, n = e & 127;
            Xs[n * PSM + kk] = __uint_as_float(f2tf32(Xb[(size_t)(k0 + kk) * NN + n0 + n]));
        }
        __syncthreads();
        const uint32_t* Wi = (const uint32_t*)Ws;
        const uint32_t* Xi = (const uint32_t*)Xs;
        #pragma unroll
        for (int ks = 0; ks < 4; ks++) {
            uint32_t a[4];
            a[0] = Wi[(16 * ow + gq) * PSM + gc + 8 * ks];
            a[1] = Wi[(16 * ow + gq + 8) * PSM + gc + 8 * ks];
            a[2] = Wi[(16 * ow + gq) * PSM + gc + 4 + 8 * ks];
            a[3] = Wi[(16 * ow + gq + 8) * PSM + gc + 4 + 8 * ks];
            #pragma unroll
            for (int nt = 0; nt < 8; nt++) {
                uint32_t b0 = Xi[(64 * nw + gq + 8 * nt) * PSM + gc + 8 * ks];
                uint32_t b1 = Xi[(64 * nw + gq + 8 * nt) * PSM + gc + 4 + 8 * ks];
                mma_tf32(cacc[nt], a, b0, b1);
            }
        }
    }
    __syncthreads();

    // scale by sn[n], stage transposed [n][o_in_head]
    const float* sb = sn + (size_t)b * NN + n0;
    #pragma unroll
    for (int nt = 0; nt < 8; nt++) {
        int nl = 64 * nw + 2 * gc + 8 * nt;
        float s0 = sb[nl], s1 = sb[nl + 1];
        Ts[nl * 68 + 16 * ow + gq]           = cacc[nt][0] * s0;
        Ts[(nl + 1) * 68 + 16 * ow + gq]     = cacc[nt][1] * s1;
        Ts[nl * 68 + 16 * ow + gq + 8]       = cacc[nt][2] * s0;
        Ts[(nl + 1) * 68 + 16 * ow + gq + 8] = cacc[nt][3] * s1;
    }
    __syncthreads();

    const int head = ob & 7;
    float* dst = (ob < 8) ? outA : outB;
    float* op = dst + ((size_t)(b * HEADS + head) * NN + n0) * 64;
    #pragma unroll
    for (int it = 0; it < 8; it++) {
        int e = it * 256 + tid;
        int row = e >> 4, c4 = e & 15;
        *(float4*)&op[(size_t)row * 64 + c4 * 4] = *(const float4*)&Ts[row * 68 + c4 * 4];
    }
    if (ob < 8 && tid < 128) {
        float ssum = 0.f;
        #pragma unroll
        for (int i = 0; i < 16; i++) {
            float4 v = *(const float4*)&Ts[tid * 68 + i * 4];
            ssum += v.x * v.x + v.y * v.y + v.z * v.z + v.w * v.w;
        }
        sq[(size_t)(b * HEADS + head) * NN + n0 + tid] = ssum;
    }
}

// ==================== plain batched GEMM (output projection, fp32 for precision) ====================
__global__ void gemm64_kernel(const float* __restrict__ W, const float* __restrict__ X,
                              float* __restrict__ Y, int O, int K, int NN) {
    const int b = blockIdx.z;
    const float* Xb = X + (size_t)b * K * NN;
    float* Yb = Y + (size_t)b * O * NN;
    const int n0 = blockIdx.x * 64, o0 = blockIdx.y * 64;
    const int tid = threadIdx.x;
    const int tx = tid & 15, ty = tid >> 4;
    __shared__ float Ws[16 * 64];
    __shared__ float Xs[16 * 64];
    float acc[4][4] = {};
    const int o_ld = tid >> 2, kq = tid & 3;
    const int k_ld = tid >> 4, n4 = tid & 15;
    for (int k0 = 0; k0 < K; k0 += 16) {
        __syncthreads();
        float4 w4 = *(const float4*)&W[(size_t)(o0 + o_ld) * K + k0 + kq * 4];
        Ws[(kq * 4 + 0) * 64 + o_ld] = w4.x;
        Ws[(kq * 4 + 1) * 64 + o_ld] = w4.y;
        Ws[(kq * 4 + 2) * 64 + o_ld] = w4.z;
        Ws[(kq * 4 + 3) * 64 + o_ld] = w4.w;
        *(float4*)&Xs[k_ld * 64 + n4 * 4] =
            *(const float4*)&Xb[(size_t)(k0 + k_ld) * NN + n0 + n4 * 4];
        __syncthreads();
        #pragma unroll
        for (int k = 0; k < 16; k++) {
            float4 a  = *(const float4*)&Ws[k * 64 + ty * 4];
            float4 bb = *(const float4*)&Xs[k * 64 + tx * 4];
            acc[0][0] += a.x * bb.x; acc[0][1] += a.x * bb.y; acc[0][2] += a.x * bb.z; acc[0][3] += a.x * bb.w;
            acc[1][0] += a.y * bb.x; acc[1][1] += a.y * bb.y; acc[1][2] += a.y * bb.z; acc[1][3] += a.y * bb.w;
            acc[2][0] += a.z * bb.x; acc[2][1] += a.z * bb.y; acc[2][2] += a.z * bb.z; acc[2][3] += a.z * bb.w;
            acc[3][0] += a.w * bb.x; acc[3][1] += a.w * bb.y; acc[3][2] += a.w * bb.z; acc[3][3] += a.w * bb.w;
        }
    }
    #pragma unroll
    for (int i = 0; i < 4; i++) {
        float4 r = make_float4(acc[i][0], acc[i][1], acc[i][2], acc[i][3]);
        *(float4*)&Yb[(size_t)(o0 + ty * 4 + i) * NN + n0 + tx * 4] = r;
    }
}

// ==================== tensor-core (mma.sync tf32) L2-distance attention ====================
// grid (NQ/128, HEADS, BATCH), 256 threads (8 warps, 16 q-rows per warp).
// smem (floats): Ks[64][76] | Vs[64][76] | Ps[8 warps][16][76]
#define SMS 76
#define ATTN_SMEM_BYTES (256 * SMS * 4)

__global__ void __launch_bounds__(256) attn_mma_kernel(
    const float* __restrict__ qT, const float* __restrict__ kT, const float* __restrict__ vT,
    const float* __restrict__ q2g, const float* __restrict__ k2g,
    const unsigned* __restrict__ mbits, float* __restrict__ ob)
{
    extern __shared__ float sm[];
    float* Ks = sm;                       // [64][SMS]
    float* Vs = sm + 64 * SMS;            // [64][SMS]
    float* Ps = sm + 128 * SMS;           // [8][16][SMS]

    const int tid = threadIdx.x;
    const int wid = tid >> 5, lane = tid & 31;
    const int gq = lane >> 2, gc = lane & 3;
    const int n0 = blockIdx.x * 128;
    const int h = blockIdx.y, b = blockIdx.z;
    const int bh = b * HEADS + h;
    const int qbase = n0 + wid * 16;

    // ---- Q A-fragments: tf32, register-resident for all KV tiles ----
    uint32_t aq[8][4];
    {
        const float* qp = qT + ((size_t)bh * NQ + qbase) * 64;
        #pragma unroll
        for (int ks = 0; ks < 8; ks++) {
            aq[ks][0] = f2tf32(qp[(size_t)gq * 64 + gc + 8 * ks]);
            aq[ks][1] = f2tf32(qp[(size_t)(gq + 8) * 64 + gc + 8 * ks]);
            aq[ks][2] = f2tf32(qp[(size_t)gq * 64 + gc + 4 + 8 * ks]);
            aq[ks][3] = f2tf32(qp[(size_t)(gq + 8) * 64 + gc + 4 + 8 * ks]);
        }
    }
    const float q2a = q2g[(size_t)bh * NQ + qbase + gq];
    const float q2b = q2g[(size_t)bh * NQ + qbase + gq + 8];
    const float* k2p = k2g + (size_t)bh * MKV;

    float oacc[8][4];
    #pragma unroll
    for (int nt = 0; nt < 8; nt++)
        #pragma unroll
        for (int i = 0; i < 4; i++) oacc[nt][i] = 0.f;
    float lA = 0.f, lB = 0.f;

    uint32_t* Pw = (uint32_t*)(Ps + wid * 16 * SMS);
    const float* kbase = kT + (size_t)bh * MKV * 64;
    const float* vbase = vT + (size_t)bh * MKV * 64;

    for (int t = 0; t < MKV / 64; t++) {
        const int m0 = t * 64;
        __syncthreads();
        // ---- stage K,V tiles [64 m][64 dd] -> smem (tf32 bits) ----
        #pragma unroll
        for (int it = 0; it < 4; it++) {
            int e = it * 256 + tid;
            int row = e >> 4, c4 = e & 15;
            float4 kv4 = *(const float4*)(kbase + (size_t)(m0 + row) * 64 + c4 * 4);
            uint32_t* dk = (uint32_t*)&Ks[row * SMS + c4 * 4];
            dk[0] = f2tf32(kv4.x); dk[1] = f2tf32(kv4.y); dk[2] = f2tf32(kv4.z); dk[3] = f2tf32(kv4.w);
            float4 vv4 = *(const float4*)(vbase + (size_t)(m0 + row) * 64 + c4 * 4);
            uint32_t* dv = (uint32_t*)&Vs[row * SMS + c4 * 4];
            dv[0] = f2tf32(vv4.x); dv[1] = f2tf32(vv4.y); dv[2] = f2tf32(vv4.z); dv[3] = f2tf32(vv4.w);
        }
        __syncthreads();

        // ---- S = Q @ K^T ----
        float sacc[8][4];
        #pragma unroll
        for (int nt = 0; nt < 8; nt++)
            #pragma unroll
            for (int i = 0; i < 4; i++) sacc[nt][i] = 0.f;
        const uint32_t* Ki = (const uint32_t*)Ks;
        #pragma unroll
        for (int ks = 0; ks < 8; ks++) {
            #pragma unroll
            for (int nt = 0; nt < 8; nt++) {
                uint32_t b0 = Ki[(gq + 8 * nt) * SMS + gc + 8 * ks];
                uint32_t b1 = Ki[(gq + 8 * nt) * SMS + gc + 4 + 8 * ks];
                mma_tf32(sacc[nt], aq[ks], b0, b1);
            }
        }

        // ---- epilogue: d2 -> -dist/8 -> exp (sim <= 0 always, so no online max) ----
        const unsigned w0 = mbits[b * (MKV / 32) + (m0 >> 5)];
        const unsigned w1 = mbits[b * (MKV / 32) + (m0 >> 5) + 1];
        #pragma unroll
        for (int nt = 0; nt < 8; nt++) {
            const int col0 = 2 * gc + 8 * nt;
            const float k20 = k2p[m0 + col0], k21 = k2p[m0 + col0 + 1];
            const unsigned bw = (nt < 4) ? w0 : w1;
            const int sh = col0 & 31;
            const unsigned bit0 = (bw >> sh) & 1u;
            const unsigned bit1 = (bw >> (sh + 1)) & 1u;
            float d00 = fmaxf(q2a + k20 - 2.f * sacc[nt][0], 1e-12f);
            float d01 = fmaxf(q2a + k21 - 2.f * sacc[nt][1], 1e-12f);
            float d10 = fmaxf(q2b + k20 - 2.f * sacc[nt][2], 1e-12f);
            float d11 = fmaxf(q2b + k21 - 2.f * sacc[nt][3], 1e-12f);
            float s00, s01, s10, s11;
            asm("sqrt.approx.f32 %0, %1;" : "=f"(s00) : "f"(d00));
            asm("sqrt.approx.f32 %0, %1;" : "=f"(s01) : "f"(d01));
            asm("sqrt.approx.f32 %0, %1;" : "=f"(s10) : "f"(d10));
            asm("sqrt.approx.f32 %0, %1;" : "=f"(s11) : "f"(d11));
            float p00 = bit0 ? exp2f(-0.18033688011112042f * s00) : 0.f;
            float p01 = bit1 ? exp2f(-0.18033688011112042f * s01) : 0.f;
            float p10 = bit0 ? exp2f(-0.18033688011112042f * s10) : 0.f;
            float p11 = bit1 ? exp2f(-0.18033688011112042f * s11) : 0.f;
            lA += p00 + p01;
            lB += p10 + p11;
            Pw[gq * SMS + col0]           = f2tf32(p00);
            Pw[gq * SMS + col0 + 1]       = f2tf32(p01);
            Pw[(gq + 8) * SMS + col0]     = f2tf32(p10);
            Pw[(gq + 8) * SMS + col0 + 1] = f2tf32(p11);
        }
        __syncwarp();

        // ---- O += P @ V ----
        const uint32_t* Vi = (const uint32_t*)Vs;
        #pragma unroll
        for (int ks = 0; ks < 8; ks++) {
            uint32_t ap[4];
            ap[0] = Pw[gq * SMS + gc + 8 * ks];
            ap[1] = Pw[(gq + 8) * SMS + gc + 8 * ks];
            ap[2] = Pw[gq * SMS + gc + 4 + 8 * ks];
            ap[3] = Pw[(gq + 8) * SMS + gc + 4 + 8 * ks];
            #pragma unroll
            for (int nt = 0; nt < 8; nt++) {
                uint32_t b0 = Vi[(gc + 8 * ks) * SMS + gq + 8 * nt];
                uint32_t b1 = Vi[(gc + 4 + 8 * ks) * SMS + gq + 8 * nt];
                mma_tf32(oacc[nt], ap, b0, b1);
            }
        }
    }

    // ---- row-sum reduce within quad, normalize, store ----
    lA += __shfl_xor_sync(0xffffffffu, lA, 1);
    lA += __shfl_xor_sync(0xffffffffu, lA, 2);
    lB += __shfl_xor_sync(0xffffffffu, lB, 1);
    lB += __shfl_xor_sync(0xffffffffu, lB, 2);
    const float iA = 1.f / lA, iB = 1.f / lB;

    float* obase = ob + ((size_t)b * DINNER + h * DHEAD) * NQ;
    const int qA = qbase + gq, qB = qA + 8;
    #pragma unroll
    for (int nt = 0; nt < 8; nt++) {
        const int dd0 = 2 * gc + 8 * nt;
        obase[(size_t)dd0 * NQ + qA]       = oacc[nt][0] * iA;
        obase[(size_t)(dd0 + 1) * NQ + qA] = oacc[nt][1] * iA;
        obase[(size_t)dd0 * NQ + qB]       = oacc[nt][2] * iB;
        obase[(size_t)(dd0 + 1) * NQ + qB] = oacc[nt][3] * iB;
    }
}

// ==================== launch ====================
extern "C" void kernel_launch(void* const* d_in, const int* in_sizes, int n_in,
                              void* d_out, int out_size) {
    const float* fmap      = (const float*)d_in[0];
    const float* context   = (const float*)d_in[1];
    const void*  mask      = d_in[2];
    const float* gamma     = (const float*)d_in[3];
    const float* gamma_ctx = (const float*)d_in[4];
    const float* Wq        = (const float*)d_in[5];
    const float* Wkv       = (const float*)d_in[6];
    const float* Wout      = (const float*)d_in[7];
    float* out = (float*)d_out;

    float *p_att, *p_qT, *p_kT, *p_vT, *p_q2, *p_k2, *p_snf, *p_snc, *p_Wqg, *p_Wkvg;
    unsigned* p_mbits;
    cudaGetSymbolAddress((void**)&p_att, g_att);
    cudaGetSymbolAddress((void**)&p_qT, g_qT);
    cudaGetSymbolAddress((void**)&p_kT, g_kT);
    cudaGetSymbolAddress((void**)&p_vT, g_vT);
    cudaGetSymbolAddress((void**)&p_q2, g_q2);
    cudaGetSymbolAddress((void**)&p_k2, g_k2);
    cudaGetSymbolAddress((void**)&p_snf, g_sn_f);
    cudaGetSymbolAddress((void**)&p_snc, g_sn_c);
    cudaGetSymbolAddress((void**)&p_Wqg, g_Wq_g);
    cudaGetSymbolAddress((void**)&p_Wkvg, g_Wkv_g);
    cudaGetSymbolAddress((void**)&p_mbits, g_maskbits);

    cudaFuncSetAttribute(attn_mma_kernel, cudaFuncAttributeMaxDynamicSharedMemorySize,
                         ATTN_SMEM_BYTES);

    // (0,1) per-column norm scales
    colscale_kernel<<<dim3(NQ / 16, BATCH), 256>>>(fmap, p_snf, NQ);
    colscale_kernel<<<dim3(MKV / 16, BATCH), 256>>>(context, p_snc, MKV);

    // (2) gamma-folded Wq, (3) tf32 Q projection  <- profiled launch (idx 3)
    wgamma_kernel<<<(DINNER * DIMC + 255) / 256, 256>>>(Wq, gamma, p_Wqg, DINNER * DIMC);
    projtc_kernel<<<dim3(NQ / 128, HEADS, BATCH), 256, PROJ_SMEM>>>(
        p_Wqg, fmap, p_snf, p_qT, p_qT, p_q2, NQ);

    // (4,5) gamma-folded Wkv + tf32 KV projection
    wgamma_kernel<<<(2 * DINNER * DIMC + 255) / 256, 256>>>(Wkv, gamma_ctx, p_Wkvg, 2 * DINNER * DIMC);
    projtc_kernel<<<dim3(MKV / 128, 2 * HEADS, BATCH), 256, PROJ_SMEM>>>(
        p_Wkvg, context, p_snc, p_kT, p_vT, p_k2, MKV);

    // (6,7) mask dtype detection + bit packing
    detect_mask_kernel<<<1, 256>>>((const unsigned int*)mask);
    maskbits_kernel<<<1, 256>>>(mask);

    // (8) fused tensor-core attention
    attn_mma_kernel<<<dim3(NQ / 128, HEADS, BATCH), 256, ATTN_SMEM_BYTES>>>(
        p_qT, p_kT, p_vT, p_q2, p_k2, p_mbits, p_att);

    // (9) output projection (fp32 for precision) -> d_out
    gemm64_kernel<<<dim3(NQ / 64, DIMC / 64, BATCH), 256>>>(Wout, p_att, out, DIMC, DINNER, NQ);
}

// round 6
// speedup vs baseline: 2.5339x; 1.1705x over previous
#include <cuda_runtime.h>
#include <math.h>
#include <cstdint>

#define BATCH 4
#define DIMC 256
#define NQ 2048
#define MKV 2048
#define HEADS 8
#define DHEAD 64
#define DINNER 512

#define C_SIM 0.18033688011112042f          /* log2(e)/8 */
#define D2_FLOOR 3.25214e-14f               /* C_SIM^2 * 1e-12 */

// ==================== scratch (device globals, no allocation) ====================
__device__ float g_att[BATCH * DINNER * NQ];      // attention output [b][o][n]
__device__ float g_qT[BATCH * DINNER * NQ];       // [b][h][n][64], tf32-rounded, *C_SIM
__device__ float g_kT[BATCH * DINNER * MKV];      // [b][h][m][64], tf32-rounded, *C_SIM
__device__ float g_vT[BATCH * DINNER * MKV];      // [b][h][m][64], tf32-rounded
__device__ float g_q2[BATCH * HEADS * NQ];        // c^2-scaled
__device__ float g_k2[BATCH * HEADS * MKV];       // c^2-scaled
__device__ float g_sn_f[BATCH * NQ];
__device__ float g_sn_c[BATCH * MKV];
__device__ unsigned g_maskbits[BATCH * MKV / 32];
__device__ int   g_mask_kind;

// ==================== small helpers ====================
__device__ __forceinline__ uint32_t f2tf32(float f) {
    uint32_t r;
    asm("cvt.rna.tf32.f32 %0, %1;" : "=r"(r) : "f"(f));
    return r;
}

__device__ __forceinline__ float tf32_trunc(float x) {
    return __uint_as_float(__float_as_uint(x) & 0xffffe000u);
}

__device__ __forceinline__ void mma_tf32(float* d, const uint32_t* a, uint32_t b0, uint32_t b1) {
    asm volatile(
        "mma.sync.aligned.m16n8k8.row.col.f32.tf32.tf32.f32 "
        "{%0,%1,%2,%3}, {%4,%5,%6,%7}, {%8,%9}, {%0,%1,%2,%3};"
        : "+f"(d[0]), "+f"(d[1]), "+f"(d[2]), "+f"(d[3])
        : "r"(a[0]), "r"(a[1]), "r"(a[2]), "r"(a[3]), "r"(b0), "r"(b1));
}

// ==================== mask dtype detection + packing ====================
__global__ void detect_mask_kernel(const unsigned int* __restrict__ w) {
    __shared__ int s_i32ok, s_f32ok;
    if (threadIdx.x == 0) { s_i32ok = 1; s_f32ok = 1; }
    __syncthreads();
    int i32ok = 1, f32ok = 1;
    for (int i = threadIdx.x; i < 2048; i += 256) {
        unsigned v = w[i];
        if (v > 1u) i32ok = 0;
        if (v != 0u && v != 0x3F800000u) f32ok = 0;
    }
    if (!i32ok) atomicAnd(&s_i32ok, 0);
    if (!f32ok) atomicAnd(&s_f32ok, 0);
    __syncthreads();
    if (threadIdx.x == 0) g_mask_kind = s_i32ok ? 0 : (s_f32ok ? 2 : 1);
}

__global__ void maskbits_kernel(const void* __restrict__ maskp) {
    int w = blockIdx.x * blockDim.x + threadIdx.x;
    if (w >= BATCH * MKV / 32) return;
    int kind = g_mask_kind;
    unsigned bits = 0;
    size_t base = (size_t)w * 32;
    for (int i = 0; i < 32; i++) {
        bool ok;
        if (kind == 0)      ok = ((const int*)maskp)[base + i] != 0;
        else if (kind == 1) ok = ((const unsigned char*)maskp)[base + i] != 0;
        else                ok = ((const float*)maskp)[base + i] != 0.f;
        bits |= (ok ? 1u : 0u) << i;
    }
    g_maskbits[w] = bits;
}

// ==================== per-column norm scale ====================
__global__ void colscale_kernel(const float* __restrict__ x, float* __restrict__ s, int NN) {
    __shared__ float red[16][17];
    const int b = blockIdx.y;
    const int n0 = blockIdx.x * 16;
    const int tx = threadIdx.x & 15, ty = threadIdx.x >> 4;
    const float* xp = x + (size_t)b * DIMC * NN + n0 + tx;
    float acc = 0.f;
    #pragma unroll
    for (int c = ty; c < DIMC; c += 16) { float v = xp[(size_t)c * NN]; acc += v * v; }
    red[ty][tx] = acc;
    __syncthreads();
    if (ty == 0) {
        float t = 0.f;
        #pragma unroll
        for (int i = 0; i < 16; i++) t += red[i][tx];
        s[(size_t)b * NN + n0 + tx] = 16.0f / fmaxf(sqrtf(t), 1e-12f);
    }
}

// ==================== tf32 mma projection: vectorized, gamma-folded, prefetched ====================
// Tile: 64 o (one head) x 128 n. 8 warps = 4 o-quarters x 2 n-halves. K-chunk 32.
// Outputs tf32-ROUNDED values (downstream mma reads them losslessly), scaled by sn[n]*sc.
#define WST 36
#define XST 140
#define PROJ_SMEM (128 * 68 * 4)

__global__ void __launch_bounds__(256) projtc_kernel(
    const float* __restrict__ W, const float* __restrict__ gam,
    const float* __restrict__ X, const float* __restrict__ sn,
    float* __restrict__ outA, float* __restrict__ outB, float* __restrict__ sq,
    int NN, float scA, float scB)
{
    extern __shared__ float ps[];
    float* Ws = ps;                 // [64][36]
    float* Xs = ps + 64 * WST;      // [32][140]
    float* Ts = ps;                 // [128][68] overlay (post-loop)

    const int tid = threadIdx.x;
    const int wid = tid >> 5, lane = tid & 31;
    const int gq = lane >> 2, gc = lane & 3;
    const int ow = wid & 3, nw = wid >> 2;
    const int n0 = blockIdx.x * 128;
    const int ob = blockIdx.y;
    const int o0 = ob * 64;
    const int b = blockIdx.z;
    const float* Xb = X + (size_t)b * DIMC * NN;

    float cacc[8][4] = {};

    float4 wpf[2], gpf[2], xpf[4];
    #pragma unroll
    for (int i = 0; i < 2; i++) {
        int e = i * 256 + tid, r = e >> 3, c4 = e & 7;
        wpf[i] = *(const float4*)&W[(size_t)(o0 + r) * DIMC + c4 * 4];
        gpf[i] = *(const float4*)&gam[c4 * 4];
    }
    #pragma unroll
    for (int i = 0; i < 4; i++) {
        int e = i * 256 + tid, kk = e >> 5, c4 = e & 31;
        xpf[i] = *(const float4*)&Xb[(size_t)kk * NN + n0 + c4 * 4];
    }

    for (int k0 = 0; k0 < DIMC; k0 += 32) {
        __syncthreads();
        #pragma unroll
        for (int i = 0; i < 2; i++) {
            int e = i * 256 + tid, r = e >> 3, c4 = e & 7;
            uint4 o;
            o.x = f2tf32(wpf[i].x * gpf[i].x);
            o.y = f2tf32(wpf[i].y * gpf[i].y);
            o.z = f2tf32(wpf[i].z * gpf[i].z);
            o.w = f2tf32(wpf[i].w * gpf[i].w);
            *(uint4*)&Ws[r * WST + c4 * 4] = o;
        }
        #pragma unroll
        for (int i = 0; i < 4; i++) {
            int e = i * 256 + tid, kk = e >> 5, c4 = e & 31;
            uint4 o;
            o.x = f2tf32(xpf[i].x);
            o.y = f2tf32(xpf[i].y);
            o.z = f2tf32(xpf[i].z);
            o.w = f2tf32(xpf[i].w);
            *(uint4*)&Xs[kk * XST + c4 * 4] = o;
        }
        if (k0 + 32 < DIMC) {
            const int k1 = k0 + 32;
            #pragma unroll
            for (int i = 0; i < 2; i++) {
                int e = i * 256 + tid, r = e >> 3, c4 = e & 7;
                wpf[i] = *(const float4*)&W[(size_t)(o0 + r) * DIMC + k1 + c4 * 4];
                gpf[i] = *(const float4*)&gam[k1 + c4 * 4];
            }
            #pragma unroll
            for (int i = 0; i < 4; i++) {
                int e = i * 256 + tid, kk = e >> 5, c4 = e & 31;
                xpf[i] = *(const float4*)&Xb[(size_t)(k1 + kk) * NN + n0 + c4 * 4];
            }
        }
        __syncthreads();
        const uint32_t* Wi = (const uint32_t*)Ws;
        const uint32_t* Xi = (const uint32_t*)Xs;
        #pragma unroll
        for (int ks = 0; ks < 4; ks++) {
            uint32_t a[4];
            a[0] = Wi[(16 * ow + gq) * WST + gc + 8 * ks];
            a[1] = Wi[(16 * ow + gq + 8) * WST + gc + 8 * ks];
            a[2] = Wi[(16 * ow + gq) * WST + gc + 4 + 8 * ks];
            a[3] = Wi[(16 * ow + gq + 8) * WST + gc + 4 + 8 * ks];
            #pragma unroll
            for (int nt = 0; nt < 8; nt++) {
                uint32_t b0 = Xi[(gc + 8 * ks) * XST + 64 * nw + gq + 8 * nt];
                uint32_t b1 = Xi[(gc + 4 + 8 * ks) * XST + 64 * nw + gq + 8 * nt];
                mma_tf32(cacc[nt], a, b0, b1);
            }
        }
    }
    __syncthreads();

    const float sc = (ob < 8) ? scA : scB;
    const float* sb = sn + (size_t)b * NN + n0;
    #pragma unroll
    for (int nt = 0; nt < 8; nt++) {
        int nl = 64 * nw + 2 * gc + 8 * nt;
        float s0 = sb[nl] * sc, s1 = sb[nl + 1] * sc;
        Ts[nl * 68 + 16 * ow + gq]           = __uint_as_float(f2tf32(cacc[nt][0] * s0));
        Ts[(nl + 1) * 68 + 16 * ow + gq]     = __uint_as_float(f2tf32(cacc[nt][1] * s1));
        Ts[nl * 68 + 16 * ow + gq + 8]       = __uint_as_float(f2tf32(cacc[nt][2] * s0));
        Ts[(nl + 1) * 68 + 16 * ow + gq + 8] = __uint_as_float(f2tf32(cacc[nt][3] * s1));
    }
    __syncthreads();

    const int head = ob & 7;
    float* dst = (ob < 8) ? outA : outB;
    float* op = dst + ((size_t)(b * HEADS + head) * NN + n0) * 64;
    #pragma unroll
    for (int it = 0; it < 8; it++) {
        int e = it * 256 + tid, row = e >> 4, c4 = e & 15;
        *(float4*)&op[(size_t)row * 64 + c4 * 4] = *(const float4*)&Ts[row * 68 + c4 * 4];
    }
    if (ob < 8 && tid < 128) {
        float ssum = 0.f;
        #pragma unroll
        for (int i = 0; i < 16; i++) {
            float4 v = *(const float4*)&Ts[tid * 68 + i * 4];
            ssum += v.x * v.x + v.y * v.y + v.z * v.z + v.w * v.w;
        }
        sq[(size_t)(b * HEADS + head) * NN + n0 + tid] = ssum;
    }
}

// ==================== plain batched GEMM (output projection, fp32 for precision) ====================
__global__ void gemm64_kernel(const float* __restrict__ W, const float* __restrict__ X,
                              float* __restrict__ Y, int O, int K, int NN) {
    const int b = blockIdx.z;
    const float* Xb = X + (size_t)b * K * NN;
    float* Yb = Y + (size_t)b * O * NN;
    const int n0 = blockIdx.x * 64, o0 = blockIdx.y * 64;
    const int tid = threadIdx.x;
    const int tx = tid & 15, ty = tid >> 4;
    __shared__ float Ws[16 * 64];
    __shared__ float Xs[16 * 64];
    float acc[4][4] = {};
    const int o_ld = tid >> 2, kq = tid & 3;
    const int k_ld = tid >> 4, n4 = tid & 15;
    for (int k0 = 0; k0 < K; k0 += 16) {
        __syncthreads();
        float4 w4 = *(const float4*)&W[(size_t)(o0 + o_ld) * K + k0 + kq * 4];
        Ws[(kq * 4 + 0) * 64 + o_ld] = w4.x;
        Ws[(kq * 4 + 1) * 64 + o_ld] = w4.y;
        Ws[(kq * 4 + 2) * 64 + o_ld] = w4.z;
        Ws[(kq * 4 + 3) * 64 + o_ld] = w4.w;
        *(float4*)&Xs[k_ld * 64 + n4 * 4] =
            *(const float4*)&Xb[(size_t)(k0 + k_ld) * NN + n0 + n4 * 4];
        __syncthreads();
        #pragma unroll
        for (int k = 0; k < 16; k++) {
            float4 a  = *(const float4*)&Ws[k * 64 + ty * 4];
            float4 bb = *(const float4*)&Xs[k * 64 + tx * 4];
            acc[0][0] += a.x * bb.x; acc[0][1] += a.x * bb.y; acc[0][2] += a.x * bb.z; acc[0][3] += a.x * bb.w;
            acc[1][0] += a.y * bb.x; acc[1][1] += a.y * bb.y; acc[1][2] += a.y * bb.z; acc[1][3] += a.y * bb.w;
            acc[2][0] += a.z * bb.x; acc[2][1] += a.z * bb.y; acc[2][2] += a.z * bb.z; acc[2][3] += a.z * bb.w;
            acc[3][0] += a.w * bb.x; acc[3][1] += a.w * bb.y; acc[3][2] += a.w * bb.z; acc[3][3] += a.w * bb.w;
        }
    }
    #pragma unroll
    for (int i = 0; i < 4; i++) {
        float4 r = make_float4(acc[i][0], acc[i][1], acc[i][2], acc[i][3]);
        *(float4*)&Yb[(size_t)(o0 + ty * 4 + i) * NN + n0 + tx * 4] = r;
    }
}

// ==================== tensor-core attention (tf32, pre-rounded inputs) ====================
// grid (NQ/128, HEADS, BATCH), 256 threads (8 warps, 16 q-rows each).
#define SMS 76
#define ATTN_SMEM_BYTES (256 * SMS * 4)

__global__ void __launch_bounds__(256) attn_mma_kernel(
    const float* __restrict__ qT, const float* __restrict__ kT, const float* __restrict__ vT,
    const float* __restrict__ q2g, const float* __restrict__ k2g,
    const unsigned* __restrict__ mbits, float* __restrict__ ob)
{
    extern __shared__ float sm[];
    float* Ks = sm;                       // [64][SMS]
    float* Vs = sm + 64 * SMS;            // [64][SMS]
    float* Ps = sm + 128 * SMS;           // [8][16][SMS]

    const int tid = threadIdx.x;
    const int wid = tid >> 5, lane = tid & 31;
    const int gq = lane >> 2, gc = lane & 3;
    const int n0 = blockIdx.x * 128;
    const int h = blockIdx.y, b = blockIdx.z;
    const int bh = b * HEADS + h;
    const int qbase = n0 + wid * 16;

    // ---- Q A-fragments: inputs pre-rounded to tf32, load raw bits ----
    uint32_t aq[8][4];
    {
        const uint32_t* qp = (const uint32_t*)(qT + ((size_t)bh * NQ + qbase) * 64);
        #pragma unroll
        for (int ks = 0; ks < 8; ks++) {
            aq[ks][0] = qp[gq * 64 + gc + 8 * ks];
            aq[ks][1] = qp[(gq + 8) * 64 + gc + 8 * ks];
            aq[ks][2] = qp[gq * 64 + gc + 4 + 8 * ks];
            aq[ks][3] = qp[(gq + 8) * 64 + gc + 4 + 8 * ks];
        }
    }
    const float q2a = q2g[(size_t)bh * NQ + qbase + gq];
    const float q2b = q2g[(size_t)bh * NQ + qbase + gq + 8];
    const float* k2p = k2g + (size_t)bh * MKV;

    float oacc[8][4];
    #pragma unroll
    for (int nt = 0; nt < 8; nt++)
        #pragma unroll
        for (int i = 0; i < 4; i++) oacc[nt][i] = 0.f;
    float lA = 0.f, lB = 0.f;

    uint32_t* Pw = (uint32_t*)(Ps + wid * 16 * SMS);
    const float* kbase = kT + (size_t)bh * MKV * 64;
    const float* vbase = vT + (size_t)bh * MKV * 64;
    const int sr = tid >> 2, sc4 = (tid & 3) * 16;

    for (int t = 0; t < MKV / 64; t++) {
        const int m0 = t * 64;
        // ---- stage K,V tiles: pure float4 copy (no conversion) ----
        float4 kt4[4], vt4[4];
        #pragma unroll
        for (int i = 0; i < 4; i++) {
            kt4[i] = *(const float4*)(kbase + (size_t)(m0 + sr) * 64 + sc4 + i * 4);
            vt4[i] = *(const float4*)(vbase + (size_t)(m0 + sr) * 64 + sc4 + i * 4);
        }
        __syncthreads();
        #pragma unroll
        for (int i = 0; i < 4; i++) {
            *(float4*)&Ks[sr * SMS + sc4 + i * 4] = kt4[i];
            *(float4*)&Vs[sr * SMS + sc4 + i * 4] = vt4[i];
        }
        __syncthreads();

        // ---- S = Q @ K^T (c^2-scaled) ----
        float sacc[8][4];
        #pragma unroll
        for (int nt = 0; nt < 8; nt++)
            #pragma unroll
            for (int i = 0; i < 4; i++) sacc[nt][i] = 0.f;
        const uint32_t* Ki = (const uint32_t*)Ks;
        #pragma unroll
        for (int ks = 0; ks < 8; ks++) {
            #pragma unroll
            for (int nt = 0; nt < 8; nt++) {
                uint32_t b0 = Ki[(gq + 8 * nt) * SMS + gc + 8 * ks];
                uint32_t b1 = Ki[(gq + 8 * nt) * SMS + gc + 4 + 8 * ks];
                mma_tf32(sacc[nt], aq[ks], b0, b1);
            }
        }

        // ---- epilogue: d2' -> sqrt = exp2 arg -> p; truncate-to-tf32 consistently ----
        const unsigned w0 = mbits[b * (MKV / 32) + (m0 >> 5)];
        const unsigned w1 = mbits[b * (MKV / 32) + (m0 >> 5) + 1];
        #pragma unroll
        for (int nt = 0; nt < 8; nt++) {
            const int col0 = 2 * gc + 8 * nt;
            const float k20 = k2p[m0 + col0], k21 = k2p[m0 + col0 + 1];
            const unsigned bw = (nt < 4) ? w0 : w1;
            const int sh = col0 & 31;
            const unsigned bit0 = (bw >> sh) & 1u;
            const unsigned bit1 = (bw >> (sh + 1)) & 1u;
            float d00 = fmaxf(fmaf(-2.f, sacc[nt][0], q2a + k20), D2_FLOOR);
            float d01 = fmaxf(fmaf(-2.f, sacc[nt][1], q2a + k21), D2_FLOOR);
            float d10 = fmaxf(fmaf(-2.f, sacc[nt][2], q2b + k20), D2_FLOOR);
            float d11 = fmaxf(fmaf(-2.f, sacc[nt][3], q2b + k21), D2_FLOOR);
            float s00, s01, s10, s11;
            asm("sqrt.approx.f32 %0, %1;" : "=f"(s00) : "f"(d00));
            asm("sqrt.approx.f32 %0, %1;" : "=f"(s01) : "f"(d01));
            asm("sqrt.approx.f32 %0, %1;" : "=f"(s10) : "f"(d10));
            asm("sqrt.approx.f32 %0, %1;" : "=f"(s11) : "f"(d11));
            float p00, p01, p10, p11;
            asm("ex2.approx.f32 %0, %1;" : "=f"(p00) : "f"(-s00));
            asm("ex2.approx.f32 %0, %1;" : "=f"(p01) : "f"(-s01));
            asm("ex2.approx.f32 %0, %1;" : "=f"(p10) : "f"(-s10));
            asm("ex2.approx.f32 %0, %1;" : "=f"(p11) : "f"(-s11));
            p00 = bit0 ? tf32_trunc(p00) : 0.f;
            p01 = bit1 ? tf32_trunc(p01) : 0.f;
            p10 = bit0 ? tf32_trunc(p10) : 0.f;
            p11 = bit1 ? tf32_trunc(p11) : 0.f;
            lA += p00 + p01;
            lB += p10 + p11;
            Pw[gq * SMS + col0]           = __float_as_uint(p00);
            Pw[gq * SMS + col0 + 1]       = __float_as_uint(p01);
            Pw[(gq + 8) * SMS + col0]     = __float_as_uint(p10);
            Pw[(gq + 8) * SMS + col0 + 1] = __float_as_uint(p11);
        }
        __syncwarp();

        // ---- O += P @ V ----
        const uint32_t* Vi = (const uint32_t*)Vs;
        #pragma unroll
        for (int ks = 0; ks < 8; ks++) {
            uint32_t ap[4];
            ap[0] = Pw[gq * SMS + gc + 8 * ks];
            ap[1] = Pw[(gq + 8) * SMS + gc + 8 * ks];
            ap[2] = Pw[gq * SMS + gc + 4 + 8 * ks];
            ap[3] = Pw[(gq + 8) * SMS + gc + 4 + 8 * ks];
            #pragma unroll
            for (int nt = 0; nt < 8; nt++) {
                uint32_t b0 = Vi[(gc + 8 * ks) * SMS + gq + 8 * nt];
                uint32_t b1 = Vi[(gc + 4 + 8 * ks) * SMS + gq + 8 * nt];
                mma_tf32(oacc[nt], ap, b0, b1);
            }
        }
    }

    lA += __shfl_xor_sync(0xffffffffu, lA, 1);
    lA += __shfl_xor_sync(0xffffffffu, lA, 2);
    lB += __shfl_xor_sync(0xffffffffu, lB, 1);
    lB += __shfl_xor_sync(0xffffffffu, lB, 2);
    const float iA = 1.f / lA, iB = 1.f / lB;

    float* obase = ob + ((size_t)b * DINNER + h * DHEAD) * NQ;
    const int qA = qbase + gq, qB = qA + 8;
    #pragma unroll
    for (int nt = 0; nt < 8; nt++) {
        const int dd0 = 2 * gc + 8 * nt;
        obase[(size_t)dd0 * NQ + qA]       = oacc[nt][0] * iA;
        obase[(size_t)(dd0 + 1) * NQ + qA] = oacc[nt][1] * iA;
        obase[(size_t)dd0 * NQ + qB]       = oacc[nt][2] * iB;
        obase[(size_t)(dd0 + 1) * NQ + qB] = oacc[nt][3] * iB;
    }
}

// ==================== launch ====================
extern "C" void kernel_launch(void* const* d_in, const int* in_sizes, int n_in,
                              void* d_out, int out_size) {
    const float* fmap      = (const float*)d_in[0];
    const float* context   = (const float*)d_in[1];
    const void*  mask      = d_in[2];
    const float* gamma     = (const float*)d_in[3];
    const float* gamma_ctx = (const float*)d_in[4];
    const float* Wq        = (const float*)d_in[5];
    const float* Wkv       = (const float*)d_in[6];
    const float* Wout      = (const float*)d_in[7];
    float* out = (float*)d_out;

    float *p_att, *p_qT, *p_kT, *p_vT, *p_q2, *p_k2, *p_snf, *p_snc;
    unsigned* p_mbits;
    cudaGetSymbolAddress((void**)&p_att, g_att);
    cudaGetSymbolAddress((void**)&p_qT, g_qT);
    cudaGetSymbolAddress((void**)&p_kT, g_kT);
    cudaGetSymbolAddress((void**)&p_vT, g_vT);
    cudaGetSymbolAddress((void**)&p_q2, g_q2);
    cudaGetSymbolAddress((void**)&p_k2, g_k2);
    cudaGetSymbolAddress((void**)&p_snf, g_sn_f);
    cudaGetSymbolAddress((void**)&p_snc, g_sn_c);
    cudaGetSymbolAddress((void**)&p_mbits, g_maskbits);

    cudaFuncSetAttribute(attn_mma_kernel, cudaFuncAttributeMaxDynamicSharedMemorySize,
                         ATTN_SMEM_BYTES);

    // (0,1) per-column norm scales
    colscale_kernel<<<dim3(NQ / 16, BATCH), 256>>>(fmap, p_snf, NQ);
    colscale_kernel<<<dim3(MKV / 16, BATCH), 256>>>(context, p_snc, MKV);

    // (2) Q projection (gamma folded, c-scaled, tf32-rounded outputs)
    projtc_kernel<<<dim3(NQ / 128, HEADS, BATCH), 256, PROJ_SMEM>>>(
        Wq, gamma, fmap, p_snf, p_qT, p_qT, p_q2, NQ, C_SIM, C_SIM);

    // (3) KV projection  <- profiled launch (idx 3); K c-scaled, V unscaled
    projtc_kernel<<<dim3(MKV / 128, 2 * HEADS, BATCH), 256, PROJ_SMEM>>>(
        Wkv, gamma_ctx, context, p_snc, p_kT, p_vT, p_k2, MKV, C_SIM, 1.0f);

    // (4,5) mask dtype detection + bit packing
    detect_mask_kernel<<<1, 256>>>((const unsigned int*)mask);
    maskbits_kernel<<<1, 256>>>(mask);

    // (6) fused tensor-core attention
    attn_mma_kernel<<<dim3(NQ / 128, HEADS, BATCH), 256, ATTN_SMEM_BYTES>>>(
        p_qT, p_kT, p_vT, p_q2, p_k2, p_mbits, p_att);

    // (7) output projection (fp32 for precision) -> d_out
    gemm64_kernel<<<dim3(NQ / 64, DIMC / 64, BATCH), 256>>>(Wout, p_att, out, DIMC, DINNER, NQ);
}

// round 9
// speedup vs baseline: 2.9807x; 1.1763x over previous
#include <cuda_runtime.h>
#include <cuda_bf16.h>
#include <math.h>
#include <cstdint>

#define BATCH 4
#define DIMC 256
#define NQ 2048
#define MKV 2048
#define HEADS 8
#define DHEAD 64
#define DINNER 512

#define C_SIM 0.18033688011112042f          /* log2(e)/8 */
#define D2_FLOOR 3.25214e-14f               /* C_SIM^2 * 1e-12 */

// ==================== scratch (device globals, no allocation) ====================
__device__ float    g_att[BATCH * DINNER * NQ];        // attention output [b][o][n] fp32
__device__ uint32_t g_qTw[BATCH * DINNER * NQ / 2];    // bf16 [b][h][n][64], *C_SIM
__device__ uint32_t g_kTw[BATCH * DINNER * MKV / 2];   // bf16 [b][h][m][64], *C_SIM
__device__ float    g_vT[BATCH * DINNER * MKV];        // fp32(tf32-rounded) [b][h][m][64]
__device__ float    g_q2[BATCH * HEADS * NQ];          // c^2-scaled, from bf16-rounded vals
__device__ float    g_k2[BATCH * HEADS * MKV];
__device__ float    g_sn_f[BATCH * NQ];
__device__ float    g_sn_c[BATCH * MKV];
__device__ unsigned g_maskbits[BATCH * MKV / 32];
__device__ int      g_mask_kind;

// ==================== small helpers ====================
__device__ __forceinline__ uint32_t f2tf32(float f) {
    uint32_t r;
    asm("cvt.rna.tf32.f32 %0, %1;" : "=r"(r) : "f"(f));
    return r;
}

__device__ __forceinline__ uint32_t pack_bf16x2(float lo, float hi) {
    uint32_t w;
    asm("cvt.rn.bf16x2.f32 %0, %1, %2;" : "=r"(w) : "f"(hi), "f"(lo));
    return w;
}

__device__ __forceinline__ float bf16r(float x) {
    return __bfloat162float(__float2bfloat16(x));
}

__device__ __forceinline__ uint32_t smem_u32(const void* p) {
    uint32_t a;
    asm("{ .reg .u64 t; cvta.to.shared.u64 t, %1; cvt.u32.u64 %0, t; }" : "=r"(a) : "l"(p));
    return a;
}

__device__ __forceinline__ void cp_async16(uint32_t dst, const void* src) {
    asm volatile("cp.async.ca.shared.global [%0], [%1], 16;" :: "r"(dst), "l"(src));
}

__device__ __forceinline__ void mma_tf32(float* d, const uint32_t* a, uint32_t b0, uint32_t b1) {
    asm volatile(
        "mma.sync.aligned.m16n8k8.row.col.f32.tf32.tf32.f32 "
        "{%0,%1,%2,%3}, {%4,%5,%6,%7}, {%8,%9}, {%0,%1,%2,%3};"
        : "+f"(d[0]), "+f"(d[1]), "+f"(d[2]), "+f"(d[3])
        : "r"(a[0]), "r"(a[1]), "r"(a[2]), "r"(a[3]), "r"(b0), "r"(b1));
}

__device__ __forceinline__ void mma_bf16(float* d, const uint32_t* a, uint32_t b0, uint32_t b1) {
    asm volatile(
        "mma.sync.aligned.m16n8k16.row.col.f32.bf16.bf16.f32 "
        "{%0,%1,%2,%3}, {%4,%5,%6,%7}, {%8,%9}, {%0,%1,%2,%3};"
        : "+f"(d[0]), "+f"(d[1]), "+f"(d[2]), "+f"(d[3])
        : "r"(a[0]), "r"(a[1]), "r"(a[2]), "r"(a[3]), "r"(b0), "r"(b1));
}

// ==================== mask dtype detection + packing ====================
__global__ void detect_mask_kernel(const unsigned int* __restrict__ w) {
    __shared__ int s_i32ok, s_f32ok;
    if (threadIdx.x == 0) { s_i32ok = 1; s_f32ok = 1; }
    __syncthreads();
    int i32ok = 1, f32ok = 1;
    for (int i = threadIdx.x; i < 2048; i += 256) {
        unsigned v = w[i];
        if (v > 1u) i32ok = 0;
        if (v != 0u && v != 0x3F800000u) f32ok = 0;
    }
    if (!i32ok) atomicAnd(&s_i32ok, 0);
    if (!f32ok) atomicAnd(&s_f32ok, 0);
    __syncthreads();
    if (threadIdx.x == 0) g_mask_kind = s_i32ok ? 0 : (s_f32ok ? 2 : 1);
}

__global__ void maskbits_kernel(const void* __restrict__ maskp) {
    int w = blockIdx.x * blockDim.x + threadIdx.x;
    if (w >= BATCH * MKV / 32) return;
    int kind = g_mask_kind;
    unsigned bits = 0;
    size_t base = (size_t)w * 32;
    for (int i = 0; i < 32; i++) {
        bool ok;
        if (kind == 0)      ok = ((const int*)maskp)[base + i] != 0;
        else if (kind == 1) ok = ((const unsigned char*)maskp)[base + i] != 0;
        else                ok = ((const float*)maskp)[base + i] != 0.f;
        bits |= (ok ? 1u : 0u) << i;
    }
    g_maskbits[w] = bits;
}

// ==================== per-column norm scale (coalesced) ====================
__global__ void colscale_kernel(const float* __restrict__ x, float* __restrict__ s, int NN) {
    __shared__ float red[8][33];
    const int b = blockIdx.y;
    const int n0 = blockIdx.x * 32;
    const int tx = threadIdx.x & 31, ty = threadIdx.x >> 5;
    const float* xp = x + (size_t)b * DIMC * NN + n0 + tx;
    float acc = 0.f;
    #pragma unroll
    for (int c = ty; c < DIMC; c += 8) { float v = xp[(size_t)c * NN]; acc += v * v; }
    red[ty][tx] = acc;
    __syncthreads();
    if (ty == 0) {
        float t = 0.f;
        #pragma unroll
        for (int i = 0; i < 8; i++) t += red[i][tx];
        s[(size_t)b * NN + n0 + tx] = 16.0f / fmaxf(sqrtf(t), 1e-12f);
    }
}

// ==================== tf32 mma projection ====================
// Tile: 64 o (one head) x 128 n. 8 warps = 4 o-quarters x 2 n-halves. K-chunk 32.
// ob<8  (Q/K): bf16 packed [bh][n][64] + sumsq (from bf16-rounded values).
// ob>=8 (V):   fp32 tf32-rounded [bh][m][64].
#define WST 36
#define XST 140
#define PROJ_SMEM (128 * 68 * 4)

__global__ void __launch_bounds__(256) projtc_kernel(
    const float* __restrict__ W, const float* __restrict__ gam,
    const float* __restrict__ X, const float* __restrict__ sn,
    uint32_t* __restrict__ outA, float* __restrict__ outBv, float* __restrict__ sq,
    int NN, float scA, float scB)
{
    extern __shared__ float ps[];
    float* Ws = ps;                 // [64][36]
    float* Xs = ps + 64 * WST;      // [32][140]
    float* Ts = ps;                 // [128][68] overlay (post-loop)

    const int tid = threadIdx.x;
    const int wid = tid >> 5, lane = tid & 31;
    const int gq = lane >> 2, gc = lane & 3;
    const int ow = wid & 3, nw = wid >> 2;
    const int n0 = blockIdx.x * 128;
    const int ob = blockIdx.y;
    const int o0 = ob * 64;
    const int b = blockIdx.z;
    const float* Xb = X + (size_t)b * DIMC * NN;

    float cacc[8][4] = {};

    float4 wpf[2], gpf[2], xpf[4];
    #pragma unroll
    for (int i = 0; i < 2; i++) {
        int e = i * 256 + tid, r = e >> 3, c4 = e & 7;
        wpf[i] = *(const float4*)&W[(size_t)(o0 + r) * DIMC + c4 * 4];
        gpf[i] = *(const float4*)&gam[c4 * 4];
    }
    #pragma unroll
    for (int i = 0; i < 4; i++) {
        int e = i * 256 + tid, kk = e >> 5, c4 = e & 31;
        xpf[i] = *(const float4*)&Xb[(size_t)kk * NN + n0 + c4 * 4];
    }

    for (int k0 = 0; k0 < DIMC; k0 += 32) {
        __syncthreads();
        #pragma unroll
        for (int i = 0; i < 2; i++) {
            int e = i * 256 + tid, r = e >> 3, c4 = e & 7;
            uint4 o;
            o.x = f2tf32(wpf[i].x * gpf[i].x);
            o.y = f2tf32(wpf[i].y * gpf[i].y);
            o.z = f2tf32(wpf[i].z * gpf[i].z);
            o.w = f2tf32(wpf[i].w * gpf[i].w);
            *(uint4*)&Ws[r * WST + c4 * 4] = o;
        }
        #pragma unroll
        for (int i = 0; i < 4; i++) {
            int e = i * 256 + tid, kk = e >> 5, c4 = e & 31;
            uint4 o;
            o.x = f2tf32(xpf[i].x);
            o.y = f2tf32(xpf[i].y);
            o.z = f2tf32(xpf[i].z);
            o.w = f2tf32(xpf[i].w);
            *(uint4*)&Xs[kk * XST + c4 * 4] = o;
        }
        if (k0 + 32 < DIMC) {
            const int k1 = k0 + 32;
            #pragma unroll
            for (int i = 0; i < 2; i++) {
                int e = i * 256 + tid, r = e >> 3, c4 = e & 7;
                wpf[i] = *(const float4*)&W[(size_t)(o0 + r) * DIMC + k1 + c4 * 4];
                gpf[i] = *(const float4*)&gam[k1 + c4 * 4];
            }
            #pragma unroll
            for (int i = 0; i < 4; i++) {
                int e = i * 256 + tid, kk = e >> 5, c4 = e & 31;
                xpf[i] = *(const float4*)&Xb[(size_t)(k1 + kk) * NN + n0 + c4 * 4];
            }
        }
        __syncthreads();
        const uint32_t* Wi = (const uint32_t*)Ws;
        const uint32_t* Xi = (const uint32_t*)Xs;
        #pragma unroll
        for (int ks = 0; ks < 4; ks++) {
            uint32_t a[4];
            a[0] = Wi[(16 * ow + gq) * WST + gc + 8 * ks];
            a[1] = Wi[(16 * ow + gq + 8) * WST + gc + 8 * ks];
            a[2] = Wi[(16 * ow + gq) * WST + gc + 4 + 8 * ks];
            a[3] = Wi[(16 * ow + gq + 8) * WST + gc + 4 + 8 * ks];
            #pragma unroll
            for (int nt = 0; nt < 8; nt++) {
                uint32_t b0 = Xi[(gc + 8 * ks) * XST + 64 * nw + gq + 8 * nt];
                uint32_t b1 = Xi[(gc + 4 + 8 * ks) * XST + 64 * nw + gq + 8 * nt];
                mma_tf32(cacc[nt], a, b0, b1);
            }
        }
    }

    const int head = ob & 7;
    const float* sb = sn + (size_t)b * NN + n0;
    __syncthreads();

    if (ob >= 8) {
        // ---- V path: fp32 tf32-rounded [bh][m][64] ----
        #pragma unroll
        for (int nt = 0; nt < 8; nt++) {
            int nl = 64 * nw + 2 * gc + 8 * nt;
            float s0 = sb[nl] * scB, s1 = sb[nl + 1] * scB;
            Ts[nl * 68 + 16 * ow + gq]           = __uint_as_float(f2tf32(cacc[nt][0] * s0));
            Ts[(nl + 1) * 68 + 16 * ow + gq]     = __uint_as_float(f2tf32(cacc[nt][1] * s1));
            Ts[nl * 68 + 16 * ow + gq + 8]       = __uint_as_float(f2tf32(cacc[nt][2] * s0));
            Ts[(nl + 1) * 68 + 16 * ow + gq + 8] = __uint_as_float(f2tf32(cacc[nt][3] * s1));
        }
        __syncthreads();
        float* op = outBv + ((size_t)(b * HEADS + head) * NN + n0) * 64;
        #pragma unroll
        for (int it = 0; it < 8; it++) {
            int e = it * 256 + tid, row = e >> 4, c4 = e & 15;
            *(float4*)&op[(size_t)row * 64 + c4 * 4] = *(const float4*)&Ts[row * 68 + c4 * 4];
        }
        return;
    }

    // ---- Q/K path: bf16 rounded, transposed staging, sumsq, packed store ----
    #pragma unroll
    for (int nt = 0; nt < 8; nt++) {
        int nl = 64 * nw + 2 * gc + 8 * nt;
        float s0 = sb[nl] * scA, s1 = sb[nl + 1] * scA;
        Ts[nl * 68 + 16 * ow + gq]           = bf16r(cacc[nt][0] * s0);
        Ts[(nl + 1) * 68 + 16 * ow + gq]     = bf16r(cacc[nt][1] * s1);
        Ts[nl * 68 + 16 * ow + gq + 8]       = bf16r(cacc[nt][2] * s0);
        Ts[(nl + 1) * 68 + 16 * ow + gq + 8] = bf16r(cacc[nt][3] * s1);
    }
    __syncthreads();

    uint32_t* op = outA + ((size_t)(b * HEADS + head) * NN + n0) * 32;
    #pragma unroll
    for (int it = 0; it < 8; it++) {
        int e = it * 256 + tid, row = e >> 4, c4 = e & 15;
        float4 v = *(const float4*)&Ts[row * 68 + c4 * 4];
        uint2 w;
        w.x = pack_bf16x2(v.x, v.y);
        w.y = pack_bf16x2(v.z, v.w);
        *(uint2*)&op[row * 32 + c4 * 2] = w;
    }
    if (tid < 128) {
        float ssum = 0.f;
        #pragma unroll
        for (int i = 0; i < 16; i++) {
            float4 v = *(const float4*)&Ts[tid * 68 + i * 4];
            ssum += v.x * v.x + v.y * v.y + v.z * v.z + v.w * v.w;
        }
        sq[(size_t)(b * HEADS + head) * NN + n0 + tid] = ssum;
    }
}

// ==================== plain batched GEMM (output projection, fp32) ====================
__global__ void gemm64_kernel(const float* __restrict__ W, const float* __restrict__ X,
                              float* __restrict__ Y, int O, int K, int NN) {
    const int b = blockIdx.z;
    const float* Xb = X + (size_t)b * K * NN;
    float* Yb = Y + (size_t)b * O * NN;
    const int n0 = blockIdx.x * 64, o0 = blockIdx.y * 64;
    const int tid = threadIdx.x;
    const int tx = tid & 15, ty = tid >> 4;
    __shared__ float Ws[16 * 64];
    __shared__ float Xs[16 * 64];
    float acc[4][4] = {};
    const int o_ld = tid >> 2, kq = tid & 3;
    const int k_ld = tid >> 4, n4 = tid & 15;
    for (int k0 = 0; k0 < K; k0 += 16) {
        __syncthreads();
        float4 w4 = *(const float4*)&W[(size_t)(o0 + o_ld) * K + k0 + kq * 4];
        Ws[(kq * 4 + 0) * 64 + o_ld] = w4.x;
        Ws[(kq * 4 + 1) * 64 + o_ld] = w4.y;
        Ws[(kq * 4 + 2) * 64 + o_ld] = w4.z;
        Ws[(kq * 4 + 3) * 64 + o_ld] = w4.w;
        *(float4*)&Xs[k_ld * 64 + n4 * 4] =
            *(const float4*)&Xb[(size_t)(k0 + k_ld) * NN + n0 + n4 * 4];
        __syncthreads();
        #pragma unroll
        for (int k = 0; k < 16; k++) {
            float4 a  = *(const float4*)&Ws[k * 64 + ty * 4];
            float4 bb = *(const float4*)&Xs[k * 64 + tx * 4];
            acc[0][0] += a.x * bb.x; acc[0][1] += a.x * bb.y; acc[0][2] += a.x * bb.z; acc[0][3] += a.x * bb.w;
            acc[1][0] += a.y * bb.x; acc[1][1] += a.y * bb.y; acc[1][2] += a.y * bb.z; acc[1][3] += a.y * bb.w;
            acc[2][0] += a.z * bb.x; acc[2][1] += a.z * bb.y; acc[2][2] += a.z * bb.z; acc[2][3] += a.z * bb.w;
            acc[3][0] += a.w * bb.x; acc[3][1] += a.w * bb.y; acc[3][2] += a.w * bb.z; acc[3][3] += a.w * bb.w;
        }
    }
    #pragma unroll
    for (int i = 0; i < 4; i++) {
        float4 r = make_float4(acc[i][0], acc[i][1], acc[i][2], acc[i][3]);
        *(float4*)&Yb[(size_t)(o0 + ty * 4 + i) * NN + n0 + tx * 4] = r;
    }
}

// ==================== attention: bf16 QK + tf32 PV, cp.async double-buffered ====================
// grid (NQ/128, HEADS, BATCH), 256 threads (8 warps, 16 q-rows each).
// smem words: K[2][64][36] | V[2][64][68] | P[8][16][68]  -> 22016 words = 88,064 B
#define KWS 36
#define VWS 68
#define PSS 68
#define OFF_V (2 * 64 * KWS)
#define OFF_P (OFF_V + 2 * 64 * VWS)
#define ATTN_SMEM_BYTES ((OFF_P + 128 * PSS) * 4)

__global__ void __launch_bounds__(256, 2) attn_mma_kernel(
    const uint32_t* __restrict__ qTw, const uint32_t* __restrict__ kTw,
    const float* __restrict__ vT,
    const float* __restrict__ q2g, const float* __restrict__ k2g,
    const unsigned* __restrict__ mbits, float* __restrict__ ob)
{
    extern __shared__ float sm[];
    uint32_t* Ksw = (uint32_t*)sm;             // [2][64][36] bf16 pairs
    float* Vs = sm + OFF_V;                     // [2][64][68] fp32
    uint32_t* Psw = (uint32_t*)(sm + OFF_P);    // [8][16][68] tf32 bits
    const uint32_t smem32 = smem_u32(sm);

    const int tid = threadIdx.x;
    const int wid = tid >> 5, lane = tid & 31;
    const int gq = lane >> 2, gc = lane & 3;
    const int n0 = blockIdx.x * 128;
    const int h = blockIdx.y, b = blockIdx.z;
    const int bh = b * HEADS + h;
    const int qbase = n0 + wid * 16;

    // ---- Q A-fragments (bf16 k16: 4 chunks) ----
    uint32_t aq[4][4];
    {
        const uint32_t* qp = qTw + ((size_t)bh * NQ + qbase) * 32;
        #pragma unroll
        for (int ks = 0; ks < 4; ks++) {
            aq[ks][0] = qp[gq * 32 + 8 * ks + gc];
            aq[ks][1] = qp[(gq + 8) * 32 + 8 * ks + gc];
            aq[ks][2] = qp[gq * 32 + 8 * ks + gc + 4];
            aq[ks][3] = qp[(gq + 8) * 32 + 8 * ks + gc + 4];
        }
    }
    const float q2a = q2g[(size_t)bh * NQ + qbase + gq];
    const float q2b = q2g[(size_t)bh * NQ + qbase + gq + 8];
    const float* k2p = k2g + (size_t)bh * MKV;

    float oacc[8][4];
    #pragma unroll
    for (int nt = 0; nt < 8; nt++)
        #pragma unroll
        for (int i = 0; i < 4; i++) oacc[nt][i] = 0.f;
    float lA = 0.f, lB = 0.f;

    uint32_t* Pw = Psw + wid * 16 * PSS;
    const uint32_t* kg = kTw + (size_t)bh * MKV * 32;
    const float* vg = vT + (size_t)bh * MKV * 64;

    // staging: K 2 cp.async/thread, V 4 cp.async/thread
    const int kr = tid >> 3, kw4 = tid & 7;     // K rows kr, kr+32; 8 quad-words/row
    const int vr = tid >> 4, vc4 = tid & 15;    // V rows vr,+16,+32,+48; 16 quad-words/row

    #define STAGE(t) do { \
        int _buf = (t) & 1; \
        uint32_t kd = smem32 + (_buf * 64 * KWS) * 4; \
        const uint32_t* ks_ = kg + (size_t)(t) * 64 * 32; \
        cp_async16(kd + ((kr) * KWS + kw4 * 4) * 4,      ks_ + (size_t)kr * 32 + kw4 * 4); \
        cp_async16(kd + ((kr + 32) * KWS + kw4 * 4) * 4, ks_ + (size_t)(kr + 32) * 32 + kw4 * 4); \
        uint32_t vd = smem32 + (OFF_V + _buf * 64 * VWS) * 4; \
        const float* vs_ = vg + (size_t)(t) * 64 * 64; \
        cp_async16(vd + ((vr) * VWS + vc4 * 4) * 4,      vs_ + (size_t)vr * 64 + vc4 * 4); \
        cp_async16(vd + ((vr + 16) * VWS + vc4 * 4) * 4, vs_ + (size_t)(vr + 16) * 64 + vc4 * 4); \
        cp_async16(vd + ((vr + 32) * VWS + vc4 * 4) * 4, vs_ + (size_t)(vr + 32) * 64 + vc4 * 4); \
        cp_async16(vd + ((vr + 48) * VWS + vc4 * 4) * 4, vs_ + (size_t)(vr + 48) * 64 + vc4 * 4); \
        asm volatile("cp.async.commit_group;" ::: "memory"); \
    } while (0)

    STAGE(0);

    for (int t = 0; t < MKV / 64; t++) {
        const int m0 = t * 64;
        asm volatile("cp.async.wait_group 0;" ::: "memory");
        __syncthreads();                       // stage(t) visible; buf[t-1] free
        if (t + 1 < MKV / 64) STAGE(t + 1);    // overlaps with compute below

        const int buf = t & 1;
        const uint32_t* Kb = Ksw + buf * 64 * KWS;
        const float* Vb = Vs + buf * 64 * VWS;

        // ---- S = Q @ K^T (bf16 k16) ----
        float sacc[8][4];
        #pragma unroll
        for (int nt = 0; nt < 8; nt++)
            #pragma unroll
            for (int i = 0; i < 4; i++) sacc[nt][i] = 0.f;
        #pragma unroll
        for (int ks = 0; ks < 4; ks++) {
            #pragma unroll
            for (int nt = 0; nt < 8; nt++) {
                uint32_t b0 = Kb[(gq + 8 * nt) * KWS + 8 * ks + gc];
                uint32_t b1 = Kb[(gq + 8 * nt) * KWS + 8 * ks + gc + 4];
                mma_bf16(sacc[nt], aq[ks], b0, b1);
            }
        }

        // ---- epilogue: d2 -> sqrt = exp2 arg -> p (tf32-RN rounded) ----
        const unsigned w0m = mbits[b * (MKV / 32) + (m0 >> 5)];
        const unsigned w1m = mbits[b * (MKV / 32) + (m0 >> 5) + 1];
        #pragma unroll
        for (int nt = 0; nt < 8; nt++) {
            const int col0 = 2 * gc + 8 * nt;
            const float k20 = k2p[m0 + col0], k21 = k2p[m0 + col0 + 1];
            const unsigned bw = (nt < 4) ? w0m : w1m;
            const int sh = col0 & 31;
            const unsigned bit0 = (bw >> sh) & 1u;
            const unsigned bit1 = (bw >> (sh + 1)) & 1u;
            float d00 = fmaxf(fmaf(-2.f, sacc[nt][0], q2a + k20), D2_FLOOR);
            float d01 = fmaxf(fmaf(-2.f, sacc[nt][1], q2a + k21), D2_FLOOR);
            float d10 = fmaxf(fmaf(-2.f, sacc[nt][2], q2b + k20), D2_FLOOR);
            float d11 = fmaxf(fmaf(-2.f, sacc[nt][3], q2b + k21), D2_FLOOR);
            float s00, s01, s10, s11;
            asm("sqrt.approx.f32 %0, %1;" : "=f"(s00) : "f"(d00));
            asm("sqrt.approx.f32 %0, %1;" : "=f"(s01) : "f"(d01));
            asm("sqrt.approx.f32 %0, %1;" : "=f"(s10) : "f"(d10));
            asm("sqrt.approx.f32 %0, %1;" : "=f"(s11) : "f"(d11));
            float p00, p01, p10, p11;
            asm("ex2.approx.f32 %0, %1;" : "=f"(p00) : "f"(-s00));
            asm("ex2.approx.f32 %0, %1;" : "=f"(p01) : "f"(-s01));
            asm("ex2.approx.f32 %0, %1;" : "=f"(p10) : "f"(-s10));
            asm("ex2.approx.f32 %0, %1;" : "=f"(p11) : "f"(-s11));
            // RN-round to tf32; accumulate the ROUNDED values (consistency)
            uint32_t r00 = bit0 ? f2tf32(p00) : 0u;
            uint32_t r01 = bit1 ? f2tf32(p01) : 0u;
            uint32_t r10 = bit0 ? f2tf32(p10) : 0u;
            uint32_t r11 = bit1 ? f2tf32(p11) : 0u;
            lA += __uint_as_float(r00) + __uint_as_float(r01);
            lB += __uint_as_float(r10) + __uint_as_float(r11);
            Pw[gq * PSS + col0]           = r00;
            Pw[gq * PSS + col0 + 1]       = r01;
            Pw[(gq + 8) * PSS + col0]     = r10;
            Pw[(gq + 8) * PSS + col0 + 1] = r11;
        }
        __syncwarp();

        // ---- O += P @ V (tf32 k8) ----
        const uint32_t* Vi = (const uint32_t*)Vb;
        #pragma unroll
        for (int ks = 0; ks < 8; ks++) {
            uint32_t ap[4];
            ap[0] = Pw[gq * PSS + gc + 8 * ks];
            ap[1] = Pw[(gq + 8) * PSS + gc + 8 * ks];
            ap[2] = Pw[gq * PSS + gc + 4 + 8 * ks];
            ap[3] = Pw[(gq + 8) * PSS + gc + 4 + 8 * ks];
            #pragma unroll
            for (int nt = 0; nt < 8; nt++) {
                uint32_t b0 = Vi[(gc + 8 * ks) * VWS + gq + 8 * nt];
                uint32_t b1 = Vi[(gc + 4 + 8 * ks) * VWS + gq + 8 * nt];
                mma_tf32(oacc[nt], ap, b0, b1);
            }
        }
    }

    lA += __shfl_xor_sync(0xffffffffu, lA, 1);
    lA += __shfl_xor_sync(0xffffffffu, lA, 2);
    lB += __shfl_xor_sync(0xffffffffu, lB, 1);
    lB += __shfl_xor_sync(0xffffffffu, lB, 2);
    const float iA = 1.f / lA, iB = 1.f / lB;

    float* obase = ob + ((size_t)b * DINNER + h * DHEAD) * NQ;
    const int qA = qbase + gq, qB = qA + 8;
    #pragma unroll
    for (int nt = 0; nt < 8; nt++) {
        const int dd0 = 2 * gc + 8 * nt;
        obase[(size_t)dd0 * NQ + qA]       = oacc[nt][0] * iA;
        obase[(size_t)(dd0 + 1) * NQ + qA] = oacc[nt][1] * iA;
        obase[(size_t)dd0 * NQ + qB]       = oacc[nt][2] * iB;
        obase[(size_t)(dd0 + 1) * NQ + qB] = oacc[nt][3] * iB;
    }
}

// ==================== launch ====================
extern "C" void kernel_launch(void* const* d_in, const int* in_sizes, int n_in,
                              void* d_out, int out_size) {
    const float* fmap      = (const float*)d_in[0];
    const float* context   = (const float*)d_in[1];
    const void*  mask      = d_in[2];
    const float* gamma     = (const float*)d_in[3];
    const float* gamma_ctx = (const float*)d_in[4];
    const float* Wq        = (const float*)d_in[5];
    const float* Wkv       = (const float*)d_in[6];
    const float* Wout      = (const float*)d_in[7];
    float* out = (float*)d_out;

    float *p_att, *p_vT, *p_q2, *p_k2, *p_snf, *p_snc;
    uint32_t *p_qTw, *p_kTw;
    unsigned* p_mbits;
    cudaGetSymbolAddress((void**)&p_att, g_att);
    cudaGetSymbolAddress((void**)&p_qTw, g_qTw);
    cudaGetSymbolAddress((void**)&p_kTw, g_kTw);
    cudaGetSymbolAddress((void**)&p_vT, g_vT);
    cudaGetSymbolAddress((void**)&p_q2, g_q2);
    cudaGetSymbolAddress((void**)&p_k2, g_k2);
    cudaGetSymbolAddress((void**)&p_snf, g_sn_f);
    cudaGetSymbolAddress((void**)&p_snc, g_sn_c);
    cudaGetSymbolAddress((void**)&p_mbits, g_maskbits);

    cudaFuncSetAttribute(attn_mma_kernel, cudaFuncAttributeMaxDynamicSharedMemorySize,
                         ATTN_SMEM_BYTES);

    // (0,1) per-column norm scales
    colscale_kernel<<<dim3(NQ / 32, BATCH), 256>>>(fmap, p_snf, NQ);
    colscale_kernel<<<dim3(MKV / 32, BATCH), 256>>>(context, p_snc, MKV);

    // (2) Q projection -> bf16 [bh][n][64] + q2
    projtc_kernel<<<dim3(NQ / 128, HEADS, BATCH), 256, PROJ_SMEM>>>(
        Wq, gamma, fmap, p_snf, p_qTw, p_vT, p_q2, NQ, C_SIM, C_SIM);

    // (3) KV projection -> K bf16 [bh][m][64] + k2, V tf32-fp32 [bh][m][64]
    projtc_kernel<<<dim3(MKV / 128, 2 * HEADS, BATCH), 256, PROJ_SMEM>>>(
        Wkv, gamma_ctx, context, p_snc, p_kTw, p_vT, p_k2, MKV, C_SIM, 1.0f);

    // (4,5) mask dtype detection + bit packing
    detect_mask_kernel<<<1, 256>>>((const unsigned int*)mask);
    maskbits_kernel<<<1, 256>>>(mask);

    // (6) attention: bf16 QK + tf32 PV, double-buffered cp.async
    attn_mma_kernel<<<dim3(NQ / 128, HEADS, BATCH), 256, ATTN_SMEM_BYTES>>>(
        p_qTw, p_kTw, p_vT, p_q2, p_k2, p_mbits, p_att);

    // (7) output projection (fp32) -> d_out
    gemm64_kernel<<<dim3(NQ / 64, DIMC / 64, BATCH), 256>>>(Wout, p_att, out, DIMC, DINNER, NQ);
}

// round 10
// speedup vs baseline: 3.2862x; 1.1025x over previous
#include <cuda_runtime.h>
#include <cuda_bf16.h>
#include <math.h>
#include <cstdint>

#define BATCH 4
#define DIMC 256
#define NQ 2048
#define MKV 2048
#define HEADS 8
#define DHEAD 64
#define DINNER 512

#define C_SIM 0.18033688011112042f          /* log2(e)/8 */
#define D2_FLOOR 3.25214e-14f               /* C_SIM^2 * 1e-12 */

// ==================== scratch (device globals, no allocation) ====================
__device__ float    g_att[BATCH * DINNER * NQ];        // attention output [b][o][n] fp32
__device__ uint32_t g_qTw[BATCH * DINNER * NQ / 2];    // bf16 [b][h][n][64], *C_SIM
__device__ uint32_t g_kTw[BATCH * DINNER * MKV / 2];   // bf16 [b][h][m][64], *C_SIM
__device__ float    g_vT[BATCH * DINNER * MKV];        // fp32(tf32-rounded) [b][h][m][64]
__device__ float    g_q2[BATCH * HEADS * NQ];
__device__ float    g_k2[BATCH * HEADS * MKV];
__device__ float    g_sn_f[BATCH * NQ];
__device__ float    g_sn_c[BATCH * MKV];
__device__ unsigned g_maskbits[BATCH * MKV / 32];

// ==================== small helpers ====================
__device__ __forceinline__ uint32_t f2tf32(float f) {
    uint32_t r;
    asm("cvt.rna.tf32.f32 %0, %1;" : "=r"(r) : "f"(f));
    return r;
}

__device__ __forceinline__ uint32_t pack_bf16x2(float lo, float hi) {
    uint32_t w;
    asm("cvt.rn.bf16x2.f32 %0, %1, %2;" : "=r"(w) : "f"(hi), "f"(lo));
    return w;
}

__device__ __forceinline__ float bf16r(float x) {
    return __bfloat162float(__float2bfloat16(x));
}

__device__ __forceinline__ uint32_t smem_u32(const void* p) {
    uint32_t a;
    asm("{ .reg .u64 t; cvta.to.shared.u64 t, %1; cvt.u32.u64 %0, t; }" : "=r"(a) : "l"(p));
    return a;
}

__device__ __forceinline__ void cp_async16(uint32_t dst, const void* src) {
    asm volatile("cp.async.ca.shared.global [%0], [%1], 16;" :: "r"(dst), "l"(src));
}

__device__ __forceinline__ void mma_tf32(float* d, const uint32_t* a, uint32_t b0, uint32_t b1) {
    asm volatile(
        "mma.sync.aligned.m16n8k8.row.col.f32.tf32.tf32.f32 "
        "{%0,%1,%2,%3}, {%4,%5,%6,%7}, {%8,%9}, {%0,%1,%2,%3};"
        : "+f"(d[0]), "+f"(d[1]), "+f"(d[2]), "+f"(d[3])
        : "r"(a[0]), "r"(a[1]), "r"(a[2]), "r"(a[3]), "r"(b0), "r"(b1));
}

__device__ __forceinline__ void mma_bf16(float* d, const uint32_t* a, uint32_t b0, uint32_t b1) {
    asm volatile(
        "mma.sync.aligned.m16n8k16.row.col.f32.bf16.bf16.f32 "
        "{%0,%1,%2,%3}, {%4,%5,%6,%7}, {%8,%9}, {%0,%1,%2,%3};"
        : "+f"(d[0]), "+f"(d[1]), "+f"(d[2]), "+f"(d[3])
        : "r"(a[0]), "r"(a[1]), "r"(a[2]), "r"(a[3]), "r"(b0), "r"(b1));
}

// ==================== mask: detect dtype + pack bits (one block) ====================
__global__ void mask_all_kernel(const void* __restrict__ maskp) {
    __shared__ int s_i32ok, s_f32ok;
    const unsigned* w = (const unsigned*)maskp;
    if (threadIdx.x == 0) { s_i32ok = 1; s_f32ok = 1; }
    __syncthreads();
    int i32ok = 1, f32ok = 1;
    for (int i = threadIdx.x; i < 2048; i += 256) {
        unsigned v = w[i];
        if (v > 1u) i32ok = 0;
        if (v != 0u && v != 0x3F800000u) f32ok = 0;
    }
    if (!i32ok) atomicAnd(&s_i32ok, 0);
    if (!f32ok) atomicAnd(&s_f32ok, 0);
    __syncthreads();
    const int kind = s_i32ok ? 0 : (s_f32ok ? 2 : 1);
    // pack: thread tid packs bit-word tid (256 words = BATCH*MKV/32)
    unsigned bits = 0;
    size_t base = (size_t)threadIdx.x * 32;
    for (int i = 0; i < 32; i++) {
        bool ok;
        if (kind == 0)      ok = ((const int*)maskp)[base + i] != 0;
        else if (kind == 1) ok = ((const unsigned char*)maskp)[base + i] != 0;
        else                ok = ((const float*)maskp)[base + i] != 0.f;
        bits |= (ok ? 1u : 0u) << i;
    }
    g_maskbits[threadIdx.x] = bits;
}

// ==================== per-column norm scales, both tensors in one launch ====================
__global__ void colscale_all_kernel(const float* __restrict__ fmap, const float* __restrict__ ctx,
                                    float* __restrict__ snf, float* __restrict__ snc) {
    __shared__ float red[8][33];
    const float* x = blockIdx.z ? ctx : fmap;
    float* s = blockIdx.z ? snc : snf;
    const int NN = 2048;
    const int b = blockIdx.y;
    const int n0 = blockIdx.x * 32;
    const int tx = threadIdx.x & 31, ty = threadIdx.x >> 5;
    const float* xp = x + (size_t)b * DIMC * NN + n0 + tx;
    float acc = 0.f;
    #pragma unroll
    for (int c = ty; c < DIMC; c += 8) { float v = xp[(size_t)c * NN]; acc += v * v; }
    red[ty][tx] = acc;
    __syncthreads();
    if (ty == 0) {
        float t = 0.f;
        #pragma unroll
        for (int i = 0; i < 8; i++) t += red[i][tx];
        s[(size_t)b * NN + n0 + tx] = 16.0f / fmaxf(sqrtf(t), 1e-12f);
    }
}

// ==================== merged tf32 mma projection (Q, K, V in one launch) ====================
// grid.y = 24: ob<8 Q (Wq/fmap), ob in [8,16) K, ob in [16,24) V (Wkv/context).
// Q/K: bf16 packed [bh][n][64] + sumsq. V: fp32 tf32-rounded [bh][m][64].
#define WST 36
#define XST 132
#define PROJ_SMEM (128 * 68 * 4)

__global__ void __launch_bounds__(256) proj_all_kernel(
    const float* __restrict__ Wq, const float* __restrict__ Wkv,
    const float* __restrict__ gamma, const float* __restrict__ gamma_ctx,
    const float* __restrict__ fmap, const float* __restrict__ context,
    const float* __restrict__ snf, const float* __restrict__ snc)
{
    extern __shared__ float ps[];
    float* Ws = ps;                 // [64][36]
    float* Xs = ps + 64 * WST;      // [32][132]
    float* Ts = ps;                 // [128][68] overlay (post-loop)

    const int tid = threadIdx.x;
    const int wid = tid >> 5, lane = tid & 31;
    const int gq = lane >> 2, gc = lane & 3;
    const int ow = wid & 3, nw = wid >> 2;
    const int n0 = blockIdx.x * 128;
    const int ob = blockIdx.y;
    const int b = blockIdx.z;
    const int NN = 2048;

    const float* W;
    const float* gam;
    const float* X;
    const float* sn;
    int o0;
    if (ob < 8) { W = Wq; gam = gamma; X = fmap; sn = g_sn_f; o0 = 64 * ob; }
    else        { W = Wkv; gam = gamma_ctx; X = context; sn = g_sn_c; o0 = 64 * (ob - 8); }
    (void)snf; (void)snc;
    const float* Xb = X + (size_t)b * DIMC * NN;

    float cacc[8][4] = {};

    float4 wpf[2], gpf[2], xpf[4];
    #pragma unroll
    for (int i = 0; i < 2; i++) {
        int e = i * 256 + tid, r = e >> 3, c4 = e & 7;
        wpf[i] = *(const float4*)&W[(size_t)(o0 + r) * DIMC + c4 * 4];
        gpf[i] = *(const float4*)&gam[c4 * 4];
    }
    #pragma unroll
    for (int i = 0; i < 4; i++) {
        int e = i * 256 + tid, kk = e >> 5, c4 = e & 31;
        xpf[i] = *(const float4*)&Xb[(size_t)kk * NN + n0 + c4 * 4];
    }

    for (int k0 = 0; k0 < DIMC; k0 += 32) {
        __syncthreads();
        #pragma unroll
        for (int i = 0; i < 2; i++) {
            int e = i * 256 + tid, r = e >> 3, c4 = e & 7;
            uint4 o;
            o.x = f2tf32(wpf[i].x * gpf[i].x);
            o.y = f2tf32(wpf[i].y * gpf[i].y);
            o.z = f2tf32(wpf[i].z * gpf[i].z);
            o.w = f2tf32(wpf[i].w * gpf[i].w);
            *(uint4*)&Ws[r * WST + c4 * 4] = o;
        }
        #pragma unroll
        for (int i = 0; i < 4; i++) {
            int e = i * 256 + tid, kk = e >> 5, c4 = e & 31;
            uint4 o;
            o.x = f2tf32(xpf[i].x);
            o.y = f2tf32(xpf[i].y);
            o.z = f2tf32(xpf[i].z);
            o.w = f2tf32(xpf[i].w);
            *(uint4*)&Xs[kk * XST + c4 * 4] = o;
        }
        if (k0 + 32 < DIMC) {
            const int k1 = k0 + 32;
            #pragma unroll
            for (int i = 0; i < 2; i++) {
                int e = i * 256 + tid, r = e >> 3, c4 = e & 7;
                wpf[i] = *(const float4*)&W[(size_t)(o0 + r) * DIMC + k1 + c4 * 4];
                gpf[i] = *(const float4*)&gam[k1 + c4 * 4];
            }
            #pragma unroll
            for (int i = 0; i < 4; i++) {
                int e = i * 256 + tid, kk = e >> 5, c4 = e & 31;
                xpf[i] = *(const float4*)&Xb[(size_t)(k1 + kk) * NN + n0 + c4 * 4];
            }
        }
        __syncthreads();
        const uint32_t* Wi = (const uint32_t*)Ws;
        const uint32_t* Xi = (const uint32_t*)Xs;
        #pragma unroll
        for (int ks = 0; ks < 4; ks++) {
            uint32_t a[4];
            a[0] = Wi[(16 * ow + gq) * WST + gc + 8 * ks];
            a[1] = Wi[(16 * ow + gq + 8) * WST + gc + 8 * ks];
            a[2] = Wi[(16 * ow + gq) * WST + gc + 4 + 8 * ks];
            a[3] = Wi[(16 * ow + gq + 8) * WST + gc + 4 + 8 * ks];
            #pragma unroll
            for (int nt = 0; nt < 8; nt++) {
                uint32_t b0 = Xi[(gc + 8 * ks) * XST + 64 * nw + gq + 8 * nt];
                uint32_t b1 = Xi[(gc + 4 + 8 * ks) * XST + 64 * nw + gq + 8 * nt];
                mma_tf32(cacc[nt], a, b0, b1);
            }
        }
    }

    const float* sb = sn + (size_t)b * NN + n0;
    __syncthreads();

    if (ob >= 16) {
        // ---- V path: fp32 tf32-rounded [bh][m][64] ----
        const int head = ob - 16;
        #pragma unroll
        for (int nt = 0; nt < 8; nt++) {
            int nl = 64 * nw + 2 * gc + 8 * nt;
            float s0 = sb[nl], s1 = sb[nl + 1];
            Ts[nl * 68 + 16 * ow + gq]           = __uint_as_float(f2tf32(cacc[nt][0] * s0));
            Ts[(nl + 1) * 68 + 16 * ow + gq]     = __uint_as_float(f2tf32(cacc[nt][1] * s1));
            Ts[nl * 68 + 16 * ow + gq + 8]       = __uint_as_float(f2tf32(cacc[nt][2] * s0));
            Ts[(nl + 1) * 68 + 16 * ow + gq + 8] = __uint_as_float(f2tf32(cacc[nt][3] * s1));
        }
        __syncthreads();
        float* op = g_vT + ((size_t)(b * HEADS + head) * NN + n0) * 64;
        #pragma unroll
        for (int it = 0; it < 8; it++) {
            int e = it * 256 + tid, row = e >> 4, c4 = e & 15;
            *(float4*)&op[(size_t)row * 64 + c4 * 4] = *(const float4*)&Ts[row * 68 + c4 * 4];
        }
        return;
    }

    // ---- Q/K path: bf16 rounded (*C_SIM), transposed staging, sumsq, packed store ----
    const int head = ob & 7;
    #pragma unroll
    for (int nt = 0; nt < 8; nt++) {
        int nl = 64 * nw + 2 * gc + 8 * nt;
        float s0 = sb[nl] * C_SIM, s1 = sb[nl + 1] * C_SIM;
        Ts[nl * 68 + 16 * ow + gq]           = bf16r(cacc[nt][0] * s0);
        Ts[(nl + 1) * 68 + 16 * ow + gq]     = bf16r(cacc[nt][1] * s1);
        Ts[nl * 68 + 16 * ow + gq + 8]       = bf16r(cacc[nt][2] * s0);
        Ts[(nl + 1) * 68 + 16 * ow + gq + 8] = bf16r(cacc[nt][3] * s1);
    }
    __syncthreads();

    uint32_t* outw = (ob < 8) ? g_qTw : g_kTw;
    float* sqp = (ob < 8) ? g_q2 : g_k2;
    uint32_t* op = outw + ((size_t)(b * HEADS + head) * NN + n0) * 32;
    #pragma unroll
    for (int it = 0; it < 8; it++) {
        int e = it * 256 + tid, row = e >> 4, c4 = e & 15;
        float4 v = *(const float4*)&Ts[row * 68 + c4 * 4];
        uint2 w;
        w.x = pack_bf16x2(v.x, v.y);
        w.y = pack_bf16x2(v.z, v.w);
        *(uint2*)&op[row * 32 + c4 * 2] = w;
    }
    if (tid < 128) {
        float ssum = 0.f;
        #pragma unroll
        for (int i = 0; i < 16; i++) {
            float4 v = *(const float4*)&Ts[tid * 68 + i * 4];
            ssum += v.x * v.x + v.y * v.y + v.z * v.z + v.w * v.w;
        }
        sqp[(size_t)(b * HEADS + head) * NN + n0 + tid] = ssum;
    }
}

// ==================== tf32 mma output projection: d_out = Wout @ att ====================
// Tile: 64 o x 128 n; K = DINNER = 512; direct float2 stores.
__global__ void __launch_bounds__(256) projout_kernel(
    const float* __restrict__ W, const float* __restrict__ X, float* __restrict__ Y)
{
    extern __shared__ float ps[];
    float* Ws = ps;                 // [64][36]
    float* Xs = ps + 64 * WST;      // [32][132]

    const int tid = threadIdx.x;
    const int wid = tid >> 5, lane = tid & 31;
    const int gq = lane >> 2, gc = lane & 3;
    const int ow = wid & 3, nw = wid >> 2;
    const int n0 = blockIdx.x * 128;
    const int o0 = blockIdx.y * 64;
    const int b = blockIdx.z;
    const int NN = 2048;
    const float* Xb = X + (size_t)b * DINNER * NN;

    float cacc[8][4] = {};

    float4 wpf[2], xpf[4];
    #pragma unroll
    for (int i = 0; i < 2; i++) {
        int e = i * 256 + tid, r = e >> 3, c4 = e & 7;
        wpf[i] = *(const float4*)&W[(size_t)(o0 + r) * DINNER + c4 * 4];
    }
    #pragma unroll
    for (int i = 0; i < 4; i++) {
        int e = i * 256 + tid, kk = e >> 5, c4 = e & 31;
        xpf[i] = *(const float4*)&Xb[(size_t)kk * NN + n0 + c4 * 4];
    }

    for (int k0 = 0; k0 < DINNER; k0 += 32) {
        __syncthreads();
        #pragma unroll
        for (int i = 0; i < 2; i++) {
            int e = i * 256 + tid, r = e >> 3, c4 = e & 7;
            uint4 o;
            o.x = f2tf32(wpf[i].x);
            o.y = f2tf32(wpf[i].y);
            o.z = f2tf32(wpf[i].z);
            o.w = f2tf32(wpf[i].w);
            *(uint4*)&Ws[r * WST + c4 * 4] = o;
        }
        #pragma unroll
        for (int i = 0; i < 4; i++) {
            int e = i * 256 + tid, kk = e >> 5, c4 = e & 31;
            uint4 o;
            o.x = f2tf32(xpf[i].x);
            o.y = f2tf32(xpf[i].y);
            o.z = f2tf32(xpf[i].z);
            o.w = f2tf32(xpf[i].w);
            *(uint4*)&Xs[kk * XST + c4 * 4] = o;
        }
        if (k0 + 32 < DINNER) {
            const int k1 = k0 + 32;
            #pragma unroll
            for (int i = 0; i < 2; i++) {
                int e = i * 256 + tid, r = e >> 3, c4 = e & 7;
                wpf[i] = *(const float4*)&W[(size_t)(o0 + r) * DINNER + k1 + c4 * 4];
            }
            #pragma unroll
            for (int i = 0; i < 4; i++) {
                int e = i * 256 + tid, kk = e >> 5, c4 = e & 31;
                xpf[i] = *(const float4*)&Xb[(size_t)(k1 + kk) * NN + n0 + c4 * 4];
            }
        }
        __syncthreads();
        const uint32_t* Wi = (const uint32_t*)Ws;
        const uint32_t* Xi = (const uint32_t*)Xs;
        #pragma unroll
        for (int ks = 0; ks < 4; ks++) {
            uint32_t a[4];
            a[0] = Wi[(16 * ow + gq) * WST + gc + 8 * ks];
            a[1] = Wi[(16 * ow + gq + 8) * WST + gc + 8 * ks];
            a[2] = Wi[(16 * ow + gq) * WST + gc + 4 + 8 * ks];
            a[3] = Wi[(16 * ow + gq + 8) * WST + gc + 4 + 8 * ks];
            #pragma unroll
            for (int nt = 0; nt < 8; nt++) {
                uint32_t b0 = Xi[(gc + 8 * ks) * XST + 64 * nw + gq + 8 * nt];
                uint32_t b1 = Xi[(gc + 4 + 8 * ks) * XST + 64 * nw + gq + 8 * nt];
                mma_tf32(cacc[nt], a, b0, b1);
            }
        }
    }

    float* yb = Y + ((size_t)b * DIMC + o0) * NN + n0;
    const int rA = 16 * ow + gq, rB = rA + 8;
    #pragma unroll
    for (int nt = 0; nt < 8; nt++) {
        const int col = 64 * nw + 2 * gc + 8 * nt;
        *(float2*)&yb[(size_t)rA * NN + col] = make_float2(cacc[nt][0], cacc[nt][1]);
        *(float2*)&yb[(size_t)rB * NN + col] = make_float2(cacc[nt][2], cacc[nt][3]);
    }
}

// ==================== attention: bf16 QK + tf32 PV, cp.async double-buffered ====================
// grid (NQ/128, HEADS, BATCH), 256 threads (8 warps, 16 q-rows each).
// smem words: K[2][64][36] | V[2][64][68] | P[8][16][68] -> 88,064 B
#define KWS 36
#define VWS 68
#define PSS 68
#define OFF_V (2 * 64 * KWS)
#define OFF_P (OFF_V + 2 * 64 * VWS)
#define ATTN_SMEM_BYTES ((OFF_P + 128 * PSS) * 4)

__global__ void __launch_bounds__(256, 2) attn_mma_kernel(
    const uint32_t* __restrict__ qTw, const uint32_t* __restrict__ kTw,
    const float* __restrict__ vT,
    const float* __restrict__ q2g, const float* __restrict__ k2g,
    const unsigned* __restrict__ mbits, float* __restrict__ ob)
{
    extern __shared__ float sm[];
    uint32_t* Ksw = (uint32_t*)sm;             // [2][64][36] bf16 pairs
    float* Vs = sm + OFF_V;                     // [2][64][68] fp32
    uint32_t* Psw = (uint32_t*)(sm + OFF_P);    // [8][16][68] tf32 bits
    const uint32_t smem32 = smem_u32(sm);

    const int tid = threadIdx.x;
    const int wid = tid >> 5, lane = tid & 31;
    const int gq = lane >> 2, gc = lane & 3;
    const int n0 = blockIdx.x * 128;
    const int h = blockIdx.y, b = blockIdx.z;
    const int bh = b * HEADS + h;
    const int qbase = n0 + wid * 16;

    // ---- Q A-fragments (bf16 k16: 4 chunks) ----
    uint32_t aq[4][4];
    {
        const uint32_t* qp = qTw + ((size_t)bh * NQ + qbase) * 32;
        #pragma unroll
        for (int ks = 0; ks < 4; ks++) {
            aq[ks][0] = qp[gq * 32 + 8 * ks + gc];
            aq[ks][1] = qp[(gq + 8) * 32 + 8 * ks + gc];
            aq[ks][2] = qp[gq * 32 + 8 * ks + gc + 4];
            aq[ks][3] = qp[(gq + 8) * 32 + 8 * ks + gc + 4];
        }
    }
    const float q2a = q2g[(size_t)bh * NQ + qbase + gq];
    const float q2b = q2g[(size_t)bh * NQ + qbase + gq + 8];
    const float* k2p = k2g + (size_t)bh * MKV;

    float oacc[8][4];
    #pragma unroll
    for (int nt = 0; nt < 8; nt++)
        #pragma unroll
        for (int i = 0; i < 4; i++) oacc[nt][i] = 0.f;
    float lA = 0.f, lB = 0.f;

    uint32_t* Pw = Psw + wid * 16 * PSS;
    const uint32_t* kg = kTw + (size_t)bh * MKV * 32;
    const float* vg = vT + (size_t)bh * MKV * 64;

    const int kr = tid >> 3, kw4 = tid & 7;
    const int vr = tid >> 4, vc4 = tid & 15;

    #define STAGE(t) do { \
        int _buf = (t) & 1; \
        uint32_t kd = smem32 + (_buf * 64 * KWS) * 4; \
        const uint32_t* ks_ = kg + (size_t)(t) * 64 * 32; \
        cp_async16(kd + ((kr) * KWS + kw4 * 4) * 4,      ks_ + (size_t)kr * 32 + kw4 * 4); \
        cp_async16(kd + ((kr + 32) * KWS + kw4 * 4) * 4, ks_ + (size_t)(kr + 32) * 32 + kw4 * 4); \
        uint32_t vd = smem32 + (OFF_V + _buf * 64 * VWS) * 4; \
        const float* vs_ = vg + (size_t)(t) * 64 * 64; \
        cp_async16(vd + ((vr) * VWS + vc4 * 4) * 4,      vs_ + (size_t)vr * 64 + vc4 * 4); \
        cp_async16(vd + ((vr + 16) * VWS + vc4 * 4) * 4, vs_ + (size_t)(vr + 16) * 64 + vc4 * 4); \
        cp_async16(vd + ((vr + 32) * VWS + vc4 * 4) * 4, vs_ + (size_t)(vr + 32) * 64 + vc4 * 4); \
        cp_async16(vd + ((vr + 48) * VWS + vc4 * 4) * 4, vs_ + (size_t)(vr + 48) * 64 + vc4 * 4); \
        asm volatile("cp.async.commit_group;" ::: "memory"); \
    } while (0)

    STAGE(0);

    for (int t = 0; t < MKV / 64; t++) {
        const int m0 = t * 64;
        asm volatile("cp.async.wait_group 0;" ::: "memory");
        __syncthreads();
        if (t + 1 < MKV / 64) STAGE(t + 1);

        const int buf = t & 1;
        const uint32_t* Kb = Ksw + buf * 64 * KWS;
        const float* Vb = Vs + buf * 64 * VWS;

        // ---- S = Q @ K^T (bf16 k16) ----
        float sacc[8][4];
        #pragma unroll
        for (int nt = 0; nt < 8; nt++)
            #pragma unroll
            for (int i = 0; i < 4; i++) sacc[nt][i] = 0.f;
        #pragma unroll
        for (int ks = 0; ks < 4; ks++) {
            #pragma unroll
            for (int nt = 0; nt < 8; nt++) {
                uint32_t b0 = Kb[(gq + 8 * nt) * KWS + 8 * ks + gc];
                uint32_t b1 = Kb[(gq + 8 * nt) * KWS + 8 * ks + gc + 4];
                mma_bf16(sacc[nt], aq[ks], b0, b1);
            }
        }

        // ---- epilogue ----
        const unsigned w0m = mbits[b * (MKV / 32) + (m0 >> 5)];
        const unsigned w1m = mbits[b * (MKV / 32) + (m0 >> 5) + 1];
        #pragma unroll
        for (int nt = 0; nt < 8; nt++) {
            const int col0 = 2 * gc + 8 * nt;
            const float k20 = k2p[m0 + col0], k21 = k2p[m0 + col0 + 1];
            const unsigned bw = (nt < 4) ? w0m : w1m;
            const int sh = col0 & 31;
            const unsigned bit0 = (bw >> sh) & 1u;
            const unsigned bit1 = (bw >> (sh + 1)) & 1u;
            float d00 = fmaxf(fmaf(-2.f, sacc[nt][0], q2a + k20), D2_FLOOR);
            float d01 = fmaxf(fmaf(-2.f, sacc[nt][1], q2a + k21), D2_FLOOR);
            float d10 = fmaxf(fmaf(-2.f, sacc[nt][2], q2b + k20), D2_FLOOR);
            float d11 = fmaxf(fmaf(-2.f, sacc[nt][3], q2b + k21), D2_FLOOR);
            float s00, s01, s10, s11;
            asm("sqrt.approx.f32 %0, %1;" : "=f"(s00) : "f"(d00));
            asm("sqrt.approx.f32 %0, %1;" : "=f"(s01) : "f"(d01));
            asm("sqrt.approx.f32 %0, %1;" : "=f"(s10) : "f"(d10));
            asm("sqrt.approx.f32 %0, %1;" : "=f"(s11) : "f"(d11));
            float p00, p01, p10, p11;
            asm("ex2.approx.f32 %0, %1;" : "=f"(p00) : "f"(-s00));
            asm("ex2.approx.f32 %0, %1;" : "=f"(p01) : "f"(-s01));
            asm("ex2.approx.f32 %0, %1;" : "=f"(p10) : "f"(-s10));
            asm("ex2.approx.f32 %0, %1;" : "=f"(p11) : "f"(-s11));
            uint32_t r00 = bit0 ? f2tf32(p00) : 0u;
            uint32_t r01 = bit1 ? f2tf32(p01) : 0u;
            uint32_t r10 = bit0 ? f2tf32(p10) : 0u;
            uint32_t r11 = bit1 ? f2tf32(p11) : 0u;
            lA += __uint_as_float(r00) + __uint_as_float(r01);
            lB += __uint_as_float(r10) + __uint_as_float(r11);
            Pw[gq * PSS + col0]           = r00;
            Pw[gq * PSS + col0 + 1]       = r01;
            Pw[(gq + 8) * PSS + col0]     = r10;
            Pw[(gq + 8) * PSS + col0 + 1] = r11;
        }
        __syncwarp();

        // ---- O += P @ V (tf32 k8) ----
        const uint32_t* Vi = (const uint32_t*)Vb;
        #pragma unroll
        for (int ks = 0; ks < 8; ks++) {
            uint32_t ap[4];
            ap[0] = Pw[gq * PSS + gc + 8 * ks];
            ap[1] = Pw[(gq + 8) * PSS + gc + 8 * ks];
            ap[2] = Pw[gq * PSS + gc + 4 + 8 * ks];
            ap[3] = Pw[(gq + 8) * PSS + gc + 4 + 8 * ks];
            #pragma unroll
            for (int nt = 0; nt < 8; nt++) {
                uint32_t b0 = Vi[(gc + 8 * ks) * VWS + gq + 8 * nt];
                uint32_t b1 = Vi[(gc + 4 + 8 * ks) * VWS + gq + 8 * nt];
                mma_tf32(oacc[nt], ap, b0, b1);
            }
        }
    }

    lA += __shfl_xor_sync(0xffffffffu, lA, 1);
    lA += __shfl_xor_sync(0xffffffffu, lA, 2);
    lB += __shfl_xor_sync(0xffffffffu, lB, 1);
    lB += __shfl_xor_sync(0xffffffffu, lB, 2);
    const float iA = 1.f / lA, iB = 1.f / lB;

    float* obase = ob + ((size_t)b * DINNER + h * DHEAD) * NQ;
    const int qA = qbase + gq, qB = qA + 8;
    #pragma unroll
    for (int nt = 0; nt < 8; nt++) {
        const int dd0 = 2 * gc + 8 * nt;
        obase[(size_t)dd0 * NQ + qA]       = oacc[nt][0] * iA;
        obase[(size_t)(dd0 + 1) * NQ + qA] = oacc[nt][1] * iA;
        obase[(size_t)dd0 * NQ + qB]       = oacc[nt][2] * iB;
        obase[(size_t)(dd0 + 1) * NQ + qB] = oacc[nt][3] * iB;
    }
}

// ==================== launch ====================
extern "C" void kernel_launch(void* const* d_in, const int* in_sizes, int n_in,
                              void* d_out, int out_size) {
    const float* fmap      = (const float*)d_in[0];
    const float* context   = (const float*)d_in[1];
    const void*  mask      = d_in[2];
    const float* gamma     = (const float*)d_in[3];
    const float* gamma_ctx = (const float*)d_in[4];
    const float* Wq        = (const float*)d_in[5];
    const float* Wkv       = (const float*)d_in[6];
    const float* Wout      = (const float*)d_in[7];
    float* out = (float*)d_out;

    float *p_att, *p_vT, *p_q2, *p_k2, *p_snf, *p_snc;
    uint32_t *p_qTw, *p_kTw;
    unsigned* p_mbits;
    cudaGetSymbolAddress((void**)&p_att, g_att);
    cudaGetSymbolAddress((void**)&p_qTw, g_qTw);
    cudaGetSymbolAddress((void**)&p_kTw, g_kTw);
    cudaGetSymbolAddress((void**)&p_vT, g_vT);
    cudaGetSymbolAddress((void**)&p_q2, g_q2);
    cudaGetSymbolAddress((void**)&p_k2, g_k2);
    cudaGetSymbolAddress((void**)&p_snf, g_sn_f);
    cudaGetSymbolAddress((void**)&p_snc, g_sn_c);
    cudaGetSymbolAddress((void**)&p_mbits, g_maskbits);

    cudaFuncSetAttribute(attn_mma_kernel, cudaFuncAttributeMaxDynamicSharedMemorySize,
                         ATTN_SMEM_BYTES);

    // (0) per-column norm scales for both tensors
    colscale_all_kernel<<<dim3(64, BATCH, 2), 256>>>(fmap, context, p_snf, p_snc);

    // (1) mask detect + pack
    mask_all_kernel<<<1, 256>>>(mask);

    // (2) merged Q/K/V projection
    proj_all_kernel<<<dim3(16, 24, BATCH), 256, PROJ_SMEM>>>(
        Wq, Wkv, gamma, gamma_ctx, fmap, context, p_snf, p_snc);

    // (3) attention  <- profiled launch (idx 3)
    attn_mma_kernel<<<dim3(NQ / 128, HEADS, BATCH), 256, ATTN_SMEM_BYTES>>>(
        p_qTw, p_kTw, p_vT, p_q2, p_k2, p_mbits, p_att);

    // (4) output projection (tf32 mma) -> d_out
    projout_kernel<<<dim3(16, 4, BATCH), 256, PROJ_SMEM>>>(Wout, p_att, out);
}